// round 11
// baseline (speedup 1.0000x reference)
#include <cuda_runtime.h>
#include <cuda_bf16.h>
#include <cstdint>

#define SLEN 4096
#define DM   1024
#define NH   16
#define DH   64
#define QKV_LD (3*DM)

// ---------------- device-global scratch (no allocs allowed) ----------------
__device__ __nv_bfloat16 g_xh[(size_t)SLEN * DM], g_xl[(size_t)SLEN * DM];     // x split [S,K]
__device__ __nv_bfloat16 g_wah[(size_t)3*DM*DM],  g_wal[(size_t)3*DM*DM];      // W_attn^T split [N,K]
__device__ __nv_bfloat16 g_wph[(size_t)DM*DM],    g_wpl[(size_t)DM*DM];        // W_proj^T split [N,K]
__device__ __nv_bfloat16 g_qh[(size_t)SLEN * QKV_LD], g_ql[(size_t)SLEN * QKV_LD]; // qkv split
__device__ __nv_bfloat16 g_ah[(size_t)SLEN * DM], g_al[(size_t)SLEN * DM];     // attn out split

// ---------------- helpers ----------------
__device__ __forceinline__ uint32_t smem_u32(const void* p) {
    uint32_t a;
    asm("{ .reg .u64 t; cvta.to.shared.u64 t, %1; cvt.u32.u64 %0, t; }" : "=r"(a) : "l"(p));
    return a;
}
__device__ __forceinline__ void cp16(uint32_t s, const void* g) {
    asm volatile("cp.async.cg.shared.global [%0], [%1], 16;" :: "r"(s), "l"(g));
}
__device__ __forceinline__ void ldsm4(uint32_t a, uint32_t r[4]) {
    asm volatile("ldmatrix.sync.aligned.m8n8.x4.shared.b16 {%0,%1,%2,%3}, [%4];"
                 : "=r"(r[0]), "=r"(r[1]), "=r"(r[2]), "=r"(r[3]) : "r"(a));
}
__device__ __forceinline__ void ldsm4t(uint32_t a, uint32_t r[4]) {
    asm volatile("ldmatrix.sync.aligned.m8n8.x4.trans.shared.b16 {%0,%1,%2,%3}, [%4];"
                 : "=r"(r[0]), "=r"(r[1]), "=r"(r[2]), "=r"(r[3]) : "r"(a));
}
__device__ __forceinline__ void mma16816(float c[4], const uint32_t a[4], uint32_t b0, uint32_t b1) {
    asm volatile("mma.sync.aligned.m16n8k16.row.col.f32.bf16.bf16.f32 "
                 "{%0,%1,%2,%3}, {%4,%5,%6,%7}, {%8,%9}, {%0,%1,%2,%3};"
                 : "+f"(c[0]), "+f"(c[1]), "+f"(c[2]), "+f"(c[3])
                 : "r"(a[0]), "r"(a[1]), "r"(a[2]), "r"(a[3]), "r"(b0), "r"(b1));
}
// pack (a->low, b->high) as bf16x2
__device__ __forceinline__ uint32_t pkf(float a, float b) {
    uint32_t r;
    asm("cvt.rn.bf16x2.f32 %0, %1, %2;" : "=r"(r) : "f"(b), "f"(a));
    return r;
}
__device__ __forceinline__ float lowf(uint32_t x)  { return __uint_as_float(x << 16); }
__device__ __forceinline__ float highf(uint32_t x) { return __uint_as_float(x & 0xFFFF0000u); }

// fast exp2 on the FMA pipe (t <= 0), rel err ~1.5e-5
__device__ __forceinline__ float fexp2(float t) {
    t = fmaxf(t, -126.f);
    float fi = floorf(t);
    float f = t - fi;
    float p = 1.53998e-4f;
    p = fmaf(p, f, 1.33336e-3f);
    p = fmaf(p, f, 9.61813e-3f);
    p = fmaf(p, f, 5.55041e-2f);
    p = fmaf(p, f, 2.40227e-1f);
    p = fmaf(p, f, 6.93147e-1f);
    p = fmaf(p, f, 1.0f);
    return p * __int_as_float(((int)fi + 127) << 23);
}

// ---------------- pre-pass: fp32 -> bf16 hi/lo split ----------------
__global__ void split_kernel(const float4* __restrict__ in, uint2* __restrict__ hi,
                             uint2* __restrict__ lo, int n4)
{
    int i = blockIdx.x * 256 + threadIdx.x;
    if (i >= n4) return;
    float4 v = in[i];
    uint32_t h01 = pkf(v.x, v.y), h23 = pkf(v.z, v.w);
    uint32_t l01 = pkf(v.x - lowf(h01), v.y - highf(h01));
    uint32_t l23 = pkf(v.z - lowf(h23), v.w - highf(h23));
    hi[i] = make_uint2(h01, h23);
    lo[i] = make_uint2(l01, l23);
}

// ---------------- pre-pass: transpose + split  W[K,N] -> T[N,K] hi/lo ----------------
__global__ void tsplit_kernel(const float* __restrict__ W, __nv_bfloat16* __restrict__ Th,
                              __nv_bfloat16* __restrict__ Tl, int K, int N)
{
    __shared__ float t[32][33];
    int bx = blockIdx.x, by = blockIdx.y;
    int x = bx * 32 + threadIdx.x;
#pragma unroll
    for (int i = 0; i < 32; i += 8)
        t[threadIdx.y + i][threadIdx.x] = W[(size_t)(by * 32 + threadIdx.y + i) * N + x];
    __syncthreads();
    int kx = by * 32 + threadIdx.x;
#pragma unroll
    for (int i = 0; i < 32; i += 8) {
        float v = t[threadIdx.x][threadIdx.y + i];
        __nv_bfloat16 h = __float2bfloat16(v);
        size_t o = (size_t)(bx * 32 + threadIdx.y + i) * K + kx;
        Th[o] = h;
        Tl[o] = __float2bfloat16(v - __bfloat162float(h));
    }
}

// ---------------------------------------------------------------------------
// mma.sync GEMM: C = (Ah+Al)[M,K] @ (Bh+Bl)[N,K]^T + bias
// 512 threads / 16 warps (4x4), warp tile 32x32, CTA tile 128x128,
// K-chunks of 64, 3-stage cp.async pipeline, ONE sync per chunk.
// Output either fp32 (Cf) or bf16 hi/lo split (Ch/Cl).
// ---------------------------------------------------------------------------
#define KC        64
#define TILE_B    16384
#define STG_B     (4 * TILE_B)          // Ah, Al, Bh, Bl per stage
#define GEMM_SMEM (3 * STG_B)           // 196608 B

__global__ __launch_bounds__(512, 1)
void mma_gemm(const __nv_bfloat16* __restrict__ Ah, const __nv_bfloat16* __restrict__ Al,
              const __nv_bfloat16* __restrict__ Bh, const __nv_bfloat16* __restrict__ Bl,
              const float* __restrict__ bias, float* __restrict__ Cf,
              __nv_bfloat16* __restrict__ Ch, __nv_bfloat16* __restrict__ Cl,
              int M, int N, int K)
{
    extern __shared__ char smem[];
    uint32_t sb = smem_u32(smem);
    int tid = threadIdx.x;
    int l   = tid & 31;
    int wid = tid >> 5;
    int bn = blockIdx.x, bm = blockIdx.y;

    // ---- loader mapping: 128 rows x (2 x 4) sixteen-byte cols per thread ----
    int rb = tid >> 2;            // 0..127 (full tile row)
    int c2 = tid & 3;             // base 16B col; covers {c2, c2+4}

    const __nv_bfloat16* A0h = Ah + (size_t)(bm * 128 + rb) * K;
    const __nv_bfloat16* A0l = Al + (size_t)(bm * 128 + rb) * K;
    const __nv_bfloat16* B0h = Bh + (size_t)(bn * 128 + rb) * K;
    const __nv_bfloat16* B0l = Bl + (size_t)(bn * 128 + rb) * K;

    auto load_chunk = [&](int c, int st) {
        uint32_t s0 = sb + (uint32_t)st * STG_B;
        size_t gofs = (size_t)c * KC;
#pragma unroll
        for (int cc = 0; cc < 2; cc++) {
            int c16 = c2 + cc * 4;
            uint32_t so = (uint32_t)rb * 128 + (uint32_t)((c16 ^ (rb & 7)) << 4);
            size_t go = gofs + (size_t)c16 * 8;
            cp16(s0 + so,              A0h + go);
            cp16(s0 + TILE_B + so,     A0l + go);
            cp16(s0 + 2 * TILE_B + so, B0h + go);
            cp16(s0 + 3 * TILE_B + so, B0l + go);
        }
        asm volatile("cp.async.commit_group;" ::: "memory");
    };

    // ---- compute mapping: warp (wm, wn) owns 32x32 ----
    int wm = wid >> 2, wn = wid & 3;
    int m0 = wm * 32, n0 = wn * 32;

    int rowA_lane = l & 15;
    int k16A      = l >> 4;
    int rowB_lane = (l & 7) + 8 * (l >> 4);
    int k16B      = (l >> 3) & 1;

    float acc[2][4][4];
#pragma unroll
    for (int mf = 0; mf < 2; mf++)
#pragma unroll
        for (int nf = 0; nf < 4; nf++)
#pragma unroll
            for (int q = 0; q < 4; q++) acc[mf][nf][q] = 0.f;

    auto compute = [&](int st) {
        uint32_t base = sb + (uint32_t)st * STG_B;
#pragma unroll
        for (int ks = 0; ks < 4; ks++) {
            uint32_t ahf[2][4], alf[2][4];
#pragma unroll
            for (int mf = 0; mf < 2; mf++) {
                uint32_t row = (uint32_t)(m0 + mf * 16 + rowA_lane);
                uint32_t off = row * 128 + (uint32_t)(((ks * 2 + k16A) ^ (row & 7)) << 4);
                ldsm4(base + off,          ahf[mf]);
                ldsm4(base + TILE_B + off, alf[mf]);
            }
            uint32_t bhf[2][4], blf[2][4];
#pragma unroll
            for (int nfp = 0; nfp < 2; nfp++) {
                uint32_t row = (uint32_t)(n0 + nfp * 16 + rowB_lane);
                uint32_t off = row * 128 + (uint32_t)(((ks * 2 + k16B) ^ (row & 7)) << 4);
                ldsm4(base + 2 * TILE_B + off, bhf[nfp]);
                ldsm4(base + 3 * TILE_B + off, blf[nfp]);
            }
#pragma unroll
            for (int mf = 0; mf < 2; mf++)
#pragma unroll
                for (int nfp = 0; nfp < 2; nfp++)
#pragma unroll
                    for (int nf = 0; nf < 2; nf++) {
                        float* c = acc[mf][nfp * 2 + nf];
                        mma16816(c, ahf[mf], bhf[nfp][2 * nf], bhf[nfp][2 * nf + 1]);
                        mma16816(c, ahf[mf], blf[nfp][2 * nf], blf[nfp][2 * nf + 1]);
                        mma16816(c, alf[mf], bhf[nfp][2 * nf], bhf[nfp][2 * nf + 1]);
                    }
        }
    };

    int NCH = K / KC;                 // 16
    load_chunk(0, 0);
    load_chunk(1, 1);
    for (int j = 0; j < NCH; j++) {
        if (j < NCH - 1)
            asm volatile("cp.async.wait_group 1;" ::: "memory");
        else
            asm volatile("cp.async.wait_group 0;" ::: "memory");
        __syncthreads();              // also orders compute(j-1) before overwrite below
        if (j + 2 < NCH) load_chunk(j + 2, (j + 2) % 3);
        compute(j % 3);
    }

    // ---- epilogue ----
#pragma unroll
    for (int mf = 0; mf < 2; mf++) {
        int r0 = bm * 128 + m0 + mf * 16 + (l >> 2);
#pragma unroll
        for (int nfi = 0; nfi < 4; nfi++) {
            int col = bn * 128 + n0 + nfi * 8 + 2 * (l & 3);
            float2 bv = *(const float2*)&bias[col];
            const float* c = acc[mf][nfi];
            float a0 = c[0] + bv.x, a1 = c[1] + bv.y;
            float a2 = c[2] + bv.x, a3 = c[3] + bv.y;
            if (Cf) {
                *(float2*)&Cf[(size_t)r0 * N + col]       = make_float2(a0, a1);
                *(float2*)&Cf[(size_t)(r0 + 8) * N + col] = make_float2(a2, a3);
            } else {
                uint32_t h0 = pkf(a0, a1), h1 = pkf(a2, a3);
                uint32_t l0 = pkf(a0 - lowf(h0), a1 - highf(h0));
                uint32_t l1 = pkf(a2 - lowf(h1), a3 - highf(h1));
                *(uint32_t*)&Ch[(size_t)r0 * N + col]       = h0;
                *(uint32_t*)&Cl[(size_t)r0 * N + col]       = l0;
                *(uint32_t*)&Ch[(size_t)(r0 + 8) * N + col] = h1;
                *(uint32_t*)&Cl[(size_t)(r0 + 8) * N + col] = l1;
            }
        }
    }
}

// ---------------------------------------------------------------------------
// mma.sync flash attention, split bf16, causal — unchanged (verified R10).
// CTA = 128 queries x 1 head, 8 warps x 16 q-rows, key blocks of 128.
// ---------------------------------------------------------------------------
#define AT_SMEM (32768 + 2 * 65536)

__global__ __launch_bounds__(256, 1)
void attn_mma(const __nv_bfloat16* __restrict__ qkh, const __nv_bfloat16* __restrict__ qkl,
              __nv_bfloat16* __restrict__ oh, __nv_bfloat16* __restrict__ ol)
{
    extern __shared__ char smem[];
    uint32_t sb = smem_u32(smem);
    const int tid = threadIdx.x;
    const int l = tid & 31;
    const int w = tid >> 5;
    int flat = (int)blockIdx.y * 32 + (int)blockIdx.x;
    const int h  = flat & 15;
    const int qb = 31 - (flat >> 4);
    const size_t hofs = (size_t)h * DH;

    {
        int rb = tid >> 2, c2 = tid & 3;
#pragma unroll
        for (int rh = 0; rh < 2; rh++)
#pragma unroll
            for (int cc = 0; cc < 2; cc++) {
                int row = rb + rh * 64, c16 = c2 + cc * 4;
                uint32_t so = (uint32_t)row * 128 + (uint32_t)((c16 ^ (row & 7)) << 4);
                size_t go = (size_t)(qb * 128 + row) * QKV_LD + hofs + c16 * 8;
                cp16(sb + so,         qkh + go);
                cp16(sb + 16384 + so, qkl + go);
            }
        asm volatile("cp.async.commit_group;" ::: "memory");
    }
    auto load_kv = [&](int kb, int st) {
        uint32_t s0 = sb + 32768 + st * 65536;
        int rb = tid >> 2, c2 = tid & 3;
#pragma unroll
        for (int rh = 0; rh < 2; rh++)
#pragma unroll
            for (int cc = 0; cc < 2; cc++) {
                int row = rb + rh * 64, c16 = c2 + cc * 4;
                uint32_t so = (uint32_t)row * 128 + (uint32_t)((c16 ^ (row & 7)) << 4);
                size_t gk = (size_t)(kb * 128 + row) * QKV_LD + DM + hofs + c16 * 8;
                size_t gv = gk + DM;
                cp16(s0 + so,         qkh + gk);
                cp16(s0 + 16384 + so, qkl + gk);
                cp16(s0 + 32768 + so, qkh + gv);
                cp16(s0 + 49152 + so, qkl + gv);
            }
        asm volatile("cp.async.commit_group;" ::: "memory");
    };
    load_kv(0, 0);

    const int g    = l >> 2;
    const int rowA = l & 15, kA = l >> 4;
    const int rowB = (l & 7) + 8 * (l >> 4), kB = (l >> 3) & 1;
    const int rowV = (l & 7) + 8 * ((l >> 3) & 1), cV = l >> 4;
    const float CE = 0.125f * 1.44269504f;

    uint32_t qfh[4][4], qfl[4][4];
    float O[8][4];
    float mrow0 = -1e30f, mrow1 = -1e30f, ls0 = 0.f, ls1 = 0.f;
#pragma unroll
    for (int i = 0; i < 8; i++)
#pragma unroll
        for (int q = 0; q < 4; q++) O[i][q] = 0.f;

    for (int j = 0; j <= qb; j++) {
        if (j < qb) {
            load_kv(j + 1, (j + 1) & 1);
            asm volatile("cp.async.wait_group 1;" ::: "memory");
        } else {
            asm volatile("cp.async.wait_group 0;" ::: "memory");
        }
        __syncthreads();
        if (j == 0) {
#pragma unroll
            for (int t = 0; t < 4; t++) {
                int row = w * 16 + rowA;
                uint32_t off = (uint32_t)row * 128 + (uint32_t)((((t * 2 + kA) ^ (row & 7))) << 4);
                ldsm4(sb + off,         qfh[t]);
                ldsm4(sb + 16384 + off, qfl[t]);
            }
        }
        uint32_t base = sb + 32768 + (uint32_t)(j & 1) * 65536;

        float S[16][4];
#pragma unroll
        for (int a = 0; a < 16; a++)
#pragma unroll
            for (int b = 0; b < 4; b++) S[a][b] = 0.f;

#pragma unroll
        for (int np = 0; np < 8; np++) {
#pragma unroll
            for (int t = 0; t < 4; t++) {
                int row = np * 16 + rowB;
                uint32_t off = (uint32_t)row * 128 + (uint32_t)((((t * 2 + kB) ^ (row & 7))) << 4);
                uint32_t kh[4], kl[4];
                ldsm4(base + off,         kh);
                ldsm4(base + 16384 + off, kl);
                mma16816(S[2 * np],     qfh[t], kh[0], kh[1]);
                mma16816(S[2 * np],     qfh[t], kl[0], kl[1]);
                mma16816(S[2 * np],     qfl[t], kh[0], kh[1]);
                mma16816(S[2 * np + 1], qfh[t], kh[2], kh[3]);
                mma16816(S[2 * np + 1], qfh[t], kl[2], kl[3]);
                mma16816(S[2 * np + 1], qfl[t], kh[2], kh[3]);
            }
        }

        if (j == qb) {
            int r0 = w * 16 + g;
#pragma unroll
            for (int nf = 0; nf < 16; nf++) {
                int c0 = nf * 8 + 2 * (l & 3);
                if (c0     > r0)     S[nf][0] = -1e30f;
                if (c0 + 1 > r0)     S[nf][1] = -1e30f;
                if (c0     > r0 + 8) S[nf][2] = -1e30f;
                if (c0 + 1 > r0 + 8) S[nf][3] = -1e30f;
            }
        }

        float mx0 = -1e30f, mx1 = -1e30f;
#pragma unroll
        for (int nf = 0; nf < 16; nf++) {
            mx0 = fmaxf(mx0, fmaxf(S[nf][0], S[nf][1]));
            mx1 = fmaxf(mx1, fmaxf(S[nf][2], S[nf][3]));
        }
        mx0 = fmaxf(mx0, __shfl_xor_sync(0xffffffffu, mx0, 1));
        mx0 = fmaxf(mx0, __shfl_xor_sync(0xffffffffu, mx0, 2));
        mx1 = fmaxf(mx1, __shfl_xor_sync(0xffffffffu, mx1, 1));
        mx1 = fmaxf(mx1, __shfl_xor_sync(0xffffffffu, mx1, 2));
        float mn0 = fmaxf(mrow0, mx0), mn1 = fmaxf(mrow1, mx1);
        float cr0 = fexp2((mrow0 - mn0) * CE), cr1 = fexp2((mrow1 - mn1) * CE);
        mrow0 = mn0; mrow1 = mn1;
        float nm0 = mn0 * CE, nm1 = mn1 * CE;
#pragma unroll
        for (int nf = 0; nf < 8; nf++) {
            O[nf][0] *= cr0; O[nf][1] *= cr0;
            O[nf][2] *= cr1; O[nf][3] *= cr1;
        }
        float s0 = 0.f, s1 = 0.f;
#pragma unroll
        for (int t = 0; t < 8; t++) {
            float p00 = fexp2(fmaf(S[2*t][0],   CE, -nm0));
            float p01 = fexp2(fmaf(S[2*t][1],   CE, -nm0));
            float p02 = fexp2(fmaf(S[2*t][2],   CE, -nm1));
            float p03 = fexp2(fmaf(S[2*t][3],   CE, -nm1));
            float p10 = fexp2(fmaf(S[2*t+1][0], CE, -nm0));
            float p11 = fexp2(fmaf(S[2*t+1][1], CE, -nm0));
            float p12 = fexp2(fmaf(S[2*t+1][2], CE, -nm1));
            float p13 = fexp2(fmaf(S[2*t+1][3], CE, -nm1));
            s0 += (p00 + p01) + (p10 + p11);
            s1 += (p02 + p03) + (p12 + p13);
            uint32_t h0 = pkf(p00, p01), h1 = pkf(p02, p03);
            uint32_t h2 = pkf(p10, p11), h3 = pkf(p12, p13);
            uint32_t e0 = pkf(p00 - lowf(h0), p01 - highf(h0));
            uint32_t e1 = pkf(p02 - lowf(h1), p03 - highf(h1));
            uint32_t e2 = pkf(p10 - lowf(h2), p11 - highf(h2));
            uint32_t e3 = pkf(p12 - lowf(h3), p13 - highf(h3));
            S[2*t][0]   = __uint_as_float(h0);
            S[2*t][1]   = __uint_as_float(h1);
            S[2*t][2]   = __uint_as_float(h2);
            S[2*t][3]   = __uint_as_float(h3);
            S[2*t+1][0] = __uint_as_float(e0);
            S[2*t+1][1] = __uint_as_float(e1);
            S[2*t+1][2] = __uint_as_float(e2);
            S[2*t+1][3] = __uint_as_float(e3);
        }
        ls0 = ls0 * cr0 + s0;
        ls1 = ls1 * cr1 + s1;

#pragma unroll
        for (int t = 0; t < 8; t++) {
            uint32_t Ahf[4] = {__float_as_uint(S[2*t][0]),   __float_as_uint(S[2*t][1]),
                               __float_as_uint(S[2*t][2]),   __float_as_uint(S[2*t][3])};
            uint32_t Alf[4] = {__float_as_uint(S[2*t+1][0]), __float_as_uint(S[2*t+1][1]),
                               __float_as_uint(S[2*t+1][2]), __float_as_uint(S[2*t+1][3])};
#pragma unroll
            for (int vp = 0; vp < 4; vp++) {
                int row = t * 16 + rowV;
                uint32_t off = (uint32_t)row * 128 + (uint32_t)((((vp * 2 + cV) ^ (row & 7))) << 4);
                uint32_t vh[4], vl[4];
                ldsm4t(base + 32768 + off, vh);
                ldsm4t(base + 49152 + off, vl);
                mma16816(O[2 * vp],     Ahf, vh[0], vh[1]);
                mma16816(O[2 * vp],     Ahf, vl[0], vl[1]);
                mma16816(O[2 * vp],     Alf, vh[0], vh[1]);
                mma16816(O[2 * vp + 1], Ahf, vh[2], vh[3]);
                mma16816(O[2 * vp + 1], Ahf, vl[2], vl[3]);
                mma16816(O[2 * vp + 1], Alf, vh[2], vh[3]);
            }
        }
        __syncthreads();
    }

    ls0 += __shfl_xor_sync(0xffffffffu, ls0, 1);
    ls0 += __shfl_xor_sync(0xffffffffu, ls0, 2);
    ls1 += __shfl_xor_sync(0xffffffffu, ls1, 1);
    ls1 += __shfl_xor_sync(0xffffffffu, ls1, 2);
    float inv0 = 1.f / ls0, inv1 = 1.f / ls1;
    int r0 = qb * 128 + w * 16 + g;
#pragma unroll
    for (int nf = 0; nf < 8; nf++) {
        int col = nf * 8 + 2 * (l & 3);
        size_t o0 = (size_t)r0 * DM + hofs + col;
        size_t o1 = (size_t)(r0 + 8) * DM + hofs + col;
        float a0 = O[nf][0] * inv0, a1 = O[nf][1] * inv0;
        float a2 = O[nf][2] * inv1, a3 = O[nf][3] * inv1;
        uint32_t h0 = pkf(a0, a1), h1 = pkf(a2, a3);
        *(uint32_t*)&oh[o0] = h0;
        *(uint32_t*)&ol[o0] = pkf(a0 - lowf(h0), a1 - highf(h0));
        *(uint32_t*)&oh[o1] = h1;
        *(uint32_t*)&ol[o1] = pkf(a2 - lowf(h1), a3 - highf(h1));
    }
}

// ---------------------------------------------------------------------------
extern "C" void kernel_launch(void* const* d_in, const int* in_sizes, int n_in,
                              void* d_out, int out_size)
{
    const float* x      = (const float*)d_in[0];
    // d_in[1] = additive causal mask — exactly causal, handled analytically
    const float* W_attn = (const float*)d_in[2];
    const float* b_attn = (const float*)d_in[3];
    const float* W_proj = (const float*)d_in[4];
    const float* b_proj = (const float*)d_in[5];
    float* out = (float*)d_out;

    __nv_bfloat16 *xh, *xl, *wah, *wal, *wph, *wpl, *qh, *ql, *ah, *al;
    cudaGetSymbolAddress((void**)&xh, g_xh);   cudaGetSymbolAddress((void**)&xl, g_xl);
    cudaGetSymbolAddress((void**)&wah, g_wah); cudaGetSymbolAddress((void**)&wal, g_wal);
    cudaGetSymbolAddress((void**)&wph, g_wph); cudaGetSymbolAddress((void**)&wpl, g_wpl);
    cudaGetSymbolAddress((void**)&qh, g_qh);   cudaGetSymbolAddress((void**)&ql, g_ql);
    cudaGetSymbolAddress((void**)&ah, g_ah);   cudaGetSymbolAddress((void**)&al, g_al);

    static bool attr_done = false;
    if (!attr_done) {
        cudaFuncSetAttribute(mma_gemm, cudaFuncAttributeMaxDynamicSharedMemorySize, GEMM_SMEM);
        cudaFuncSetAttribute(attn_mma, cudaFuncAttributeMaxDynamicSharedMemorySize, AT_SMEM);
        attr_done = true;
    }

    // pre-pass
    int n4x = SLEN * DM / 4;
    split_kernel<<<(n4x + 255) / 256, 256>>>((const float4*)x, (uint2*)xh, (uint2*)xl, n4x);
    tsplit_kernel<<<dim3(3 * DM / 32, DM / 32), dim3(32, 8)>>>(W_attn, wah, wal, DM, 3 * DM);
    tsplit_kernel<<<dim3(DM / 32, DM / 32), dim3(32, 8)>>>(W_proj, wph, wpl, DM, DM);

    // 1) QKV projection -> bf16 split qkv
    mma_gemm<<<dim3(3 * DM / 128, SLEN / 128), 512, GEMM_SMEM>>>(
        xh, xl, wah, wal, b_attn, nullptr, qh, ql, SLEN, 3 * DM, DM);

    // 2) tensor-core flash attention -> bf16 split output
    attn_mma<<<dim3(32, 16), 256, AT_SMEM>>>(qh, ql, ah, al);

    // 3) output projection -> fp32
    mma_gemm<<<dim3(DM / 128, SLEN / 128), 512, GEMM_SMEM>>>(
        ah, al, wph, wpl, b_proj, out, nullptr, nullptr, SLEN, DM, DM);
}

// round 12
// speedup vs baseline: 1.0233x; 1.0233x over previous
#include <cuda_runtime.h>
#include <cuda_bf16.h>
#include <cstdint>

#define SLEN 4096
#define DM   1024
#define NH   16
#define DH   64
#define QKV_LD (3*DM)

// ---------------- device-global scratch (no allocs allowed) ----------------
__device__ __nv_bfloat16 g_xh[(size_t)SLEN * DM], g_xl[(size_t)SLEN * DM];     // x split [S,K]
__device__ __nv_bfloat16 g_wah[(size_t)3*DM*DM],  g_wal[(size_t)3*DM*DM];      // W_attn^T split [N,K]
__device__ __nv_bfloat16 g_wph[(size_t)DM*DM],    g_wpl[(size_t)DM*DM];        // W_proj^T split [N,K]
__device__ __nv_bfloat16 g_qh[(size_t)SLEN * QKV_LD], g_ql[(size_t)SLEN * QKV_LD]; // qkv split
__device__ __nv_bfloat16 g_ah[(size_t)SLEN * DM], g_al[(size_t)SLEN * DM];     // attn out split

// ---------------- helpers ----------------
__device__ __forceinline__ uint32_t smem_u32(const void* p) {
    uint32_t a;
    asm("{ .reg .u64 t; cvta.to.shared.u64 t, %1; cvt.u32.u64 %0, t; }" : "=r"(a) : "l"(p));
    return a;
}
__device__ __forceinline__ void cp16(uint32_t s, const void* g) {
    asm volatile("cp.async.cg.shared.global [%0], [%1], 16;" :: "r"(s), "l"(g));
}
__device__ __forceinline__ void ldsm4(uint32_t a, uint32_t r[4]) {
    asm volatile("ldmatrix.sync.aligned.m8n8.x4.shared.b16 {%0,%1,%2,%3}, [%4];"
                 : "=r"(r[0]), "=r"(r[1]), "=r"(r[2]), "=r"(r[3]) : "r"(a));
}
__device__ __forceinline__ void ldsm4t(uint32_t a, uint32_t r[4]) {
    asm volatile("ldmatrix.sync.aligned.m8n8.x4.trans.shared.b16 {%0,%1,%2,%3}, [%4];"
                 : "=r"(r[0]), "=r"(r[1]), "=r"(r[2]), "=r"(r[3]) : "r"(a));
}
__device__ __forceinline__ void mma16816(float c[4], const uint32_t a[4], uint32_t b0, uint32_t b1) {
    asm volatile("mma.sync.aligned.m16n8k16.row.col.f32.bf16.bf16.f32 "
                 "{%0,%1,%2,%3}, {%4,%5,%6,%7}, {%8,%9}, {%0,%1,%2,%3};"
                 : "+f"(c[0]), "+f"(c[1]), "+f"(c[2]), "+f"(c[3])
                 : "r"(a[0]), "r"(a[1]), "r"(a[2]), "r"(a[3]), "r"(b0), "r"(b1));
}
// pack (a->low, b->high) as bf16x2
__device__ __forceinline__ uint32_t pkf(float a, float b) {
    uint32_t r;
    asm("cvt.rn.bf16x2.f32 %0, %1, %2;" : "=r"(r) : "f"(b), "f"(a));
    return r;
}
__device__ __forceinline__ float lowf(uint32_t x)  { return __uint_as_float(x << 16); }
__device__ __forceinline__ float highf(uint32_t x) { return __uint_as_float(x & 0xFFFF0000u); }

// fast exp2 on the FMA pipe (t <= 0), rel err ~1.5e-5
__device__ __forceinline__ float fexp2(float t) {
    t = fmaxf(t, -126.f);
    float fi = floorf(t);
    float f = t - fi;
    float p = 1.53998e-4f;
    p = fmaf(p, f, 1.33336e-3f);
    p = fmaf(p, f, 9.61813e-3f);
    p = fmaf(p, f, 5.55041e-2f);
    p = fmaf(p, f, 2.40227e-1f);
    p = fmaf(p, f, 6.93147e-1f);
    p = fmaf(p, f, 1.0f);
    return p * __int_as_float(((int)fi + 127) << 23);
}

// ---------------- pre-pass: fp32 -> bf16 hi/lo split ----------------
__global__ void split_kernel(const float4* __restrict__ in, uint2* __restrict__ hi,
                             uint2* __restrict__ lo, int n4)
{
    int i = blockIdx.x * 256 + threadIdx.x;
    if (i >= n4) return;
    float4 v = in[i];
    uint32_t h01 = pkf(v.x, v.y), h23 = pkf(v.z, v.w);
    uint32_t l01 = pkf(v.x - lowf(h01), v.y - highf(h01));
    uint32_t l23 = pkf(v.z - lowf(h23), v.w - highf(h23));
    hi[i] = make_uint2(h01, h23);
    lo[i] = make_uint2(l01, l23);
}

// ---------------- pre-pass: transpose + split  W[K,N] -> T[N,K] hi/lo ----------------
__global__ void tsplit_kernel(const float* __restrict__ W, __nv_bfloat16* __restrict__ Th,
                              __nv_bfloat16* __restrict__ Tl, int K, int N)
{
    __shared__ float t[32][33];
    int bx = blockIdx.x, by = blockIdx.y;
    int x = bx * 32 + threadIdx.x;
#pragma unroll
    for (int i = 0; i < 32; i += 8)
        t[threadIdx.y + i][threadIdx.x] = W[(size_t)(by * 32 + threadIdx.y + i) * N + x];
    __syncthreads();
    int kx = by * 32 + threadIdx.x;
#pragma unroll
    for (int i = 0; i < 32; i += 8) {
        float v = t[threadIdx.x][threadIdx.y + i];
        __nv_bfloat16 h = __float2bfloat16(v);
        size_t o = (size_t)(bx * 32 + threadIdx.y + i) * K + kx;
        Th[o] = h;
        Tl[o] = __float2bfloat16(v - __bfloat162float(h));
    }
}

// ---------------------------------------------------------------------------
// mma.sync GEMM: C = (Ah+Al)[M,K] @ (Bh+Bl)[N,K]^T + bias
// 256 threads / 8 warps (4x2), warp tile 32x64 (proven 1:4 ldsm:mma ratio),
// K-chunks of 32 (64B rows, XOR-4 swizzle on (row>>1)), 3-stage cp.async,
// one sync per chunk, 96KB smem -> 2 CTAs per SM.
// OUT_F32 selects fp32 epilogue vs bf16 hi/lo split epilogue (compile-time).
// ---------------------------------------------------------------------------
#define KC        32
#define TILE_B    8192                  // 128 rows * 64 bytes
#define STG_B     (4 * TILE_B)          // Ah, Al, Bh, Bl per stage
#define GEMM_SMEM (3 * STG_B)           // 98304 B

template<bool OUT_F32>
__global__ __launch_bounds__(256, 2)
void mma_gemm(const __nv_bfloat16* __restrict__ Ah, const __nv_bfloat16* __restrict__ Al,
              const __nv_bfloat16* __restrict__ Bh, const __nv_bfloat16* __restrict__ Bl,
              const float* __restrict__ bias, float* __restrict__ Cf,
              __nv_bfloat16* __restrict__ Ch, __nv_bfloat16* __restrict__ Cl,
              int M, int N, int K)
{
    extern __shared__ char smem[];
    uint32_t sb = smem_u32(smem);
    int tid = threadIdx.x;
    int l   = tid & 31;
    int wid = tid >> 5;
    int bn = blockIdx.x, bm = blockIdx.y;

    // ---- loader mapping: 2 threads per row; cols {tid&1, (tid&1)+2} ----
    int rb = tid >> 1;                 // 0..127
    int cb = tid & 1;                  // base 16B col

    const __nv_bfloat16* A0h = Ah + (size_t)(bm * 128 + rb) * K;
    const __nv_bfloat16* A0l = Al + (size_t)(bm * 128 + rb) * K;
    const __nv_bfloat16* B0h = Bh + (size_t)(bn * 128 + rb) * K;
    const __nv_bfloat16* B0l = Bl + (size_t)(bn * 128 + rb) * K;

    auto load_chunk = [&](int c, int st) {
        uint32_t s0 = sb + (uint32_t)st * STG_B;
        size_t gofs = (size_t)c * KC;
#pragma unroll
        for (int cc = 0; cc < 2; cc++) {
            int c16 = cb + cc * 2;
            uint32_t so = (uint32_t)rb * 64 + (uint32_t)((c16 ^ ((rb >> 1) & 3)) << 4);
            size_t go = gofs + (size_t)c16 * 8;
            cp16(s0 + so,              A0h + go);
            cp16(s0 + TILE_B + so,     A0l + go);
            cp16(s0 + 2 * TILE_B + so, B0h + go);
            cp16(s0 + 3 * TILE_B + so, B0l + go);
        }
        asm volatile("cp.async.commit_group;" ::: "memory");
    };

    // ---- compute mapping: warp (wm, wn) owns 32x64 ----
    int wm = wid >> 1, wn = wid & 1;
    int m0 = wm * 32, n0 = wn * 64;

    int rowA_lane = l & 15;
    int k16A      = l >> 4;
    int rowB_lane = (l & 7) + 8 * (l >> 4);
    int k16B      = (l >> 3) & 1;

    float acc[2][8][4];
#pragma unroll
    for (int mf = 0; mf < 2; mf++)
#pragma unroll
        for (int nf = 0; nf < 8; nf++)
#pragma unroll
            for (int q = 0; q < 4; q++) acc[mf][nf][q] = 0.f;

    auto compute = [&](int st) {
        uint32_t base = sb + (uint32_t)st * STG_B;
#pragma unroll
        for (int ks = 0; ks < 2; ks++) {
            uint32_t ahf[2][4], alf[2][4];
#pragma unroll
            for (int mf = 0; mf < 2; mf++) {
                uint32_t row = (uint32_t)(m0 + mf * 16 + rowA_lane);
                uint32_t off = row * 64 + (uint32_t)(((ks * 2 + k16A) ^ ((row >> 1) & 3)) << 4);
                ldsm4(base + off,          ahf[mf]);
                ldsm4(base + TILE_B + off, alf[mf]);
            }
#pragma unroll
            for (int nfp = 0; nfp < 4; nfp++) {
                uint32_t row = (uint32_t)(n0 + nfp * 16 + rowB_lane);
                uint32_t off = row * 64 + (uint32_t)(((ks * 2 + k16B) ^ ((row >> 1) & 3)) << 4);
                uint32_t bhf[4], blf[4];
                ldsm4(base + 2 * TILE_B + off, bhf);
                ldsm4(base + 3 * TILE_B + off, blf);
#pragma unroll
                for (int mf = 0; mf < 2; mf++)
#pragma unroll
                    for (int nf = 0; nf < 2; nf++) {
                        float* c = acc[mf][nfp * 2 + nf];
                        mma16816(c, ahf[mf], bhf[2 * nf], bhf[2 * nf + 1]);
                        mma16816(c, ahf[mf], blf[2 * nf], blf[2 * nf + 1]);
                        mma16816(c, alf[mf], bhf[2 * nf], bhf[2 * nf + 1]);
                    }
            }
        }
    };

    int NCH = K / KC;                 // 32
    load_chunk(0, 0);
    load_chunk(1, 1);
    for (int j = 0; j < NCH; j++) {
        if (j < NCH - 1)
            asm volatile("cp.async.wait_group 1;" ::: "memory");
        else
            asm volatile("cp.async.wait_group 0;" ::: "memory");
        __syncthreads();              // also orders compute(j-1) before overwrite below
        if (j + 2 < NCH) load_chunk(j + 2, (j + 2) % 3);
        compute(j % 3);
    }

    // ---- epilogue ----
#pragma unroll
    for (int mf = 0; mf < 2; mf++) {
        int r0 = bm * 128 + m0 + mf * 16 + (l >> 2);
#pragma unroll
        for (int nfp = 0; nfp < 4; nfp++) {
#pragma unroll
            for (int nf = 0; nf < 2; nf++) {
                int col = bn * 128 + n0 + nfp * 16 + nf * 8 + 2 * (l & 3);
                float2 bv = *(const float2*)&bias[col];
                const float* c = acc[mf][nfp * 2 + nf];
                float a0 = c[0] + bv.x, a1 = c[1] + bv.y;
                float a2 = c[2] + bv.x, a3 = c[3] + bv.y;
                if (OUT_F32) {
                    *(float2*)&Cf[(size_t)r0 * N + col]       = make_float2(a0, a1);
                    *(float2*)&Cf[(size_t)(r0 + 8) * N + col] = make_float2(a2, a3);
                } else {
                    uint32_t h0 = pkf(a0, a1), h1 = pkf(a2, a3);
                    uint32_t l0 = pkf(a0 - lowf(h0), a1 - highf(h0));
                    uint32_t l1 = pkf(a2 - lowf(h1), a3 - highf(h1));
                    *(uint32_t*)&Ch[(size_t)r0 * N + col]       = h0;
                    *(uint32_t*)&Cl[(size_t)r0 * N + col]       = l0;
                    *(uint32_t*)&Ch[(size_t)(r0 + 8) * N + col] = h1;
                    *(uint32_t*)&Cl[(size_t)(r0 + 8) * N + col] = l1;
                }
            }
        }
    }
}

// ---------------------------------------------------------------------------
// mma.sync flash attention, split bf16, causal — unchanged (verified R10).
// CTA = 128 queries x 1 head, 8 warps x 16 q-rows, key blocks of 128.
// ---------------------------------------------------------------------------
#define AT_SMEM (32768 + 2 * 65536)

__global__ __launch_bounds__(256, 1)
void attn_mma(const __nv_bfloat16* __restrict__ qkh, const __nv_bfloat16* __restrict__ qkl,
              __nv_bfloat16* __restrict__ oh, __nv_bfloat16* __restrict__ ol)
{
    extern __shared__ char smem[];
    uint32_t sb = smem_u32(smem);
    const int tid = threadIdx.x;
    const int l = tid & 31;
    const int w = tid >> 5;
    int flat = (int)blockIdx.y * 32 + (int)blockIdx.x;
    const int h  = flat & 15;
    const int qb = 31 - (flat >> 4);
    const size_t hofs = (size_t)h * DH;

    {
        int rb = tid >> 2, c2 = tid & 3;
#pragma unroll
        for (int rh = 0; rh < 2; rh++)
#pragma unroll
            for (int cc = 0; cc < 2; cc++) {
                int row = rb + rh * 64, c16 = c2 + cc * 4;
                uint32_t so = (uint32_t)row * 128 + (uint32_t)((c16 ^ (row & 7)) << 4);
                size_t go = (size_t)(qb * 128 + row) * QKV_LD + hofs + c16 * 8;
                cp16(sb + so,         qkh + go);
                cp16(sb + 16384 + so, qkl + go);
            }
        asm volatile("cp.async.commit_group;" ::: "memory");
    }
    auto load_kv = [&](int kb, int st) {
        uint32_t s0 = sb + 32768 + st * 65536;
        int rb = tid >> 2, c2 = tid & 3;
#pragma unroll
        for (int rh = 0; rh < 2; rh++)
#pragma unroll
            for (int cc = 0; cc < 2; cc++) {
                int row = rb + rh * 64, c16 = c2 + cc * 4;
                uint32_t so = (uint32_t)row * 128 + (uint32_t)((c16 ^ (row & 7)) << 4);
                size_t gk = (size_t)(kb * 128 + row) * QKV_LD + DM + hofs + c16 * 8;
                size_t gv = gk + DM;
                cp16(s0 + so,         qkh + gk);
                cp16(s0 + 16384 + so, qkl + gk);
                cp16(s0 + 32768 + so, qkh + gv);
                cp16(s0 + 49152 + so, qkl + gv);
            }
        asm volatile("cp.async.commit_group;" ::: "memory");
    };
    load_kv(0, 0);

    const int g    = l >> 2;
    const int rowA = l & 15, kA = l >> 4;
    const int rowB = (l & 7) + 8 * (l >> 4), kB = (l >> 3) & 1;
    const int rowV = (l & 7) + 8 * ((l >> 3) & 1), cV = l >> 4;
    const float CE = 0.125f * 1.44269504f;

    uint32_t qfh[4][4], qfl[4][4];
    float O[8][4];
    float mrow0 = -1e30f, mrow1 = -1e30f, ls0 = 0.f, ls1 = 0.f;
#pragma unroll
    for (int i = 0; i < 8; i++)
#pragma unroll
        for (int q = 0; q < 4; q++) O[i][q] = 0.f;

    for (int j = 0; j <= qb; j++) {
        if (j < qb) {
            load_kv(j + 1, (j + 1) & 1);
            asm volatile("cp.async.wait_group 1;" ::: "memory");
        } else {
            asm volatile("cp.async.wait_group 0;" ::: "memory");
        }
        __syncthreads();
        if (j == 0) {
#pragma unroll
            for (int t = 0; t < 4; t++) {
                int row = w * 16 + rowA;
                uint32_t off = (uint32_t)row * 128 + (uint32_t)((((t * 2 + kA) ^ (row & 7))) << 4);
                ldsm4(sb + off,         qfh[t]);
                ldsm4(sb + 16384 + off, qfl[t]);
            }
        }
        uint32_t base = sb + 32768 + (uint32_t)(j & 1) * 65536;

        float S[16][4];
#pragma unroll
        for (int a = 0; a < 16; a++)
#pragma unroll
            for (int b = 0; b < 4; b++) S[a][b] = 0.f;

#pragma unroll
        for (int np = 0; np < 8; np++) {
#pragma unroll
            for (int t = 0; t < 4; t++) {
                int row = np * 16 + rowB;
                uint32_t off = (uint32_t)row * 128 + (uint32_t)((((t * 2 + kB) ^ (row & 7))) << 4);
                uint32_t kh[4], kl[4];
                ldsm4(base + off,         kh);
                ldsm4(base + 16384 + off, kl);
                mma16816(S[2 * np],     qfh[t], kh[0], kh[1]);
                mma16816(S[2 * np],     qfh[t], kl[0], kl[1]);
                mma16816(S[2 * np],     qfl[t], kh[0], kh[1]);
                mma16816(S[2 * np + 1], qfh[t], kh[2], kh[3]);
                mma16816(S[2 * np + 1], qfh[t], kl[2], kl[3]);
                mma16816(S[2 * np + 1], qfl[t], kh[2], kh[3]);
            }
        }

        if (j == qb) {
            int r0 = w * 16 + g;
#pragma unroll
            for (int nf = 0; nf < 16; nf++) {
                int c0 = nf * 8 + 2 * (l & 3);
                if (c0     > r0)     S[nf][0] = -1e30f;
                if (c0 + 1 > r0)     S[nf][1] = -1e30f;
                if (c0     > r0 + 8) S[nf][2] = -1e30f;
                if (c0 + 1 > r0 + 8) S[nf][3] = -1e30f;
            }
        }

        float mx0 = -1e30f, mx1 = -1e30f;
#pragma unroll
        for (int nf = 0; nf < 16; nf++) {
            mx0 = fmaxf(mx0, fmaxf(S[nf][0], S[nf][1]));
            mx1 = fmaxf(mx1, fmaxf(S[nf][2], S[nf][3]));
        }
        mx0 = fmaxf(mx0, __shfl_xor_sync(0xffffffffu, mx0, 1));
        mx0 = fmaxf(mx0, __shfl_xor_sync(0xffffffffu, mx0, 2));
        mx1 = fmaxf(mx1, __shfl_xor_sync(0xffffffffu, mx1, 1));
        mx1 = fmaxf(mx1, __shfl_xor_sync(0xffffffffu, mx1, 2));
        float mn0 = fmaxf(mrow0, mx0), mn1 = fmaxf(mrow1, mx1);
        float cr0 = fexp2((mrow0 - mn0) * CE), cr1 = fexp2((mrow1 - mn1) * CE);
        mrow0 = mn0; mrow1 = mn1;
        float nm0 = mn0 * CE, nm1 = mn1 * CE;
#pragma unroll
        for (int nf = 0; nf < 8; nf++) {
            O[nf][0] *= cr0; O[nf][1] *= cr0;
            O[nf][2] *= cr1; O[nf][3] *= cr1;
        }
        float s0 = 0.f, s1 = 0.f;
#pragma unroll
        for (int t = 0; t < 8; t++) {
            float p00 = fexp2(fmaf(S[2*t][0],   CE, -nm0));
            float p01 = fexp2(fmaf(S[2*t][1],   CE, -nm0));
            float p02 = fexp2(fmaf(S[2*t][2],   CE, -nm1));
            float p03 = fexp2(fmaf(S[2*t][3],   CE, -nm1));
            float p10 = fexp2(fmaf(S[2*t+1][0], CE, -nm0));
            float p11 = fexp2(fmaf(S[2*t+1][1], CE, -nm0));
            float p12 = fexp2(fmaf(S[2*t+1][2], CE, -nm1));
            float p13 = fexp2(fmaf(S[2*t+1][3], CE, -nm1));
            s0 += (p00 + p01) + (p10 + p11);
            s1 += (p02 + p03) + (p12 + p13);
            uint32_t h0 = pkf(p00, p01), h1 = pkf(p02, p03);
            uint32_t h2 = pkf(p10, p11), h3 = pkf(p12, p13);
            uint32_t e0 = pkf(p00 - lowf(h0), p01 - highf(h0));
            uint32_t e1 = pkf(p02 - lowf(h1), p03 - highf(h1));
            uint32_t e2 = pkf(p10 - lowf(h2), p11 - highf(h2));
            uint32_t e3 = pkf(p12 - lowf(h3), p13 - highf(h3));
            S[2*t][0]   = __uint_as_float(h0);
            S[2*t][1]   = __uint_as_float(h1);
            S[2*t][2]   = __uint_as_float(h2);
            S[2*t][3]   = __uint_as_float(h3);
            S[2*t+1][0] = __uint_as_float(e0);
            S[2*t+1][1] = __uint_as_float(e1);
            S[2*t+1][2] = __uint_as_float(e2);
            S[2*t+1][3] = __uint_as_float(e3);
        }
        ls0 = ls0 * cr0 + s0;
        ls1 = ls1 * cr1 + s1;

#pragma unroll
        for (int t = 0; t < 8; t++) {
            uint32_t Ahf[4] = {__float_as_uint(S[2*t][0]),   __float_as_uint(S[2*t][1]),
                               __float_as_uint(S[2*t][2]),   __float_as_uint(S[2*t][3])};
            uint32_t Alf[4] = {__float_as_uint(S[2*t+1][0]), __float_as_uint(S[2*t+1][1]),
                               __float_as_uint(S[2*t+1][2]), __float_as_uint(S[2*t+1][3])};
#pragma unroll
            for (int vp = 0; vp < 4; vp++) {
                int row = t * 16 + rowV;
                uint32_t off = (uint32_t)row * 128 + (uint32_t)((((vp * 2 + cV) ^ (row & 7))) << 4);
                uint32_t vh[4], vl[4];
                ldsm4t(base + 32768 + off, vh);
                ldsm4t(base + 49152 + off, vl);
                mma16816(O[2 * vp],     Ahf, vh[0], vh[1]);
                mma16816(O[2 * vp],     Ahf, vl[0], vl[1]);
                mma16816(O[2 * vp],     Alf, vh[0], vh[1]);
                mma16816(O[2 * vp + 1], Ahf, vh[2], vh[3]);
                mma16816(O[2 * vp + 1], Ahf, vl[2], vl[3]);
                mma16816(O[2 * vp + 1], Alf, vh[2], vh[3]);
            }
        }
        __syncthreads();
    }

    ls0 += __shfl_xor_sync(0xffffffffu, ls0, 1);
    ls0 += __shfl_xor_sync(0xffffffffu, ls0, 2);
    ls1 += __shfl_xor_sync(0xffffffffu, ls1, 1);
    ls1 += __shfl_xor_sync(0xffffffffu, ls1, 2);
    float inv0 = 1.f / ls0, inv1 = 1.f / ls1;
    int r0 = qb * 128 + w * 16 + g;
#pragma unroll
    for (int nf = 0; nf < 8; nf++) {
        int col = nf * 8 + 2 * (l & 3);
        size_t o0 = (size_t)r0 * DM + hofs + col;
        size_t o1 = (size_t)(r0 + 8) * DM + hofs + col;
        float a0 = O[nf][0] * inv0, a1 = O[nf][1] * inv0;
        float a2 = O[nf][2] * inv1, a3 = O[nf][3] * inv1;
        uint32_t h0 = pkf(a0, a1), h1 = pkf(a2, a3);
        *(uint32_t*)&oh[o0] = h0;
        *(uint32_t*)&ol[o0] = pkf(a0 - lowf(h0), a1 - highf(h0));
        *(uint32_t*)&oh[o1] = h1;
        *(uint32_t*)&ol[o1] = pkf(a2 - lowf(h1), a3 - highf(h1));
    }
}

// ---------------------------------------------------------------------------
extern "C" void kernel_launch(void* const* d_in, const int* in_sizes, int n_in,
                              void* d_out, int out_size)
{
    const float* x      = (const float*)d_in[0];
    // d_in[1] = additive causal mask — exactly causal, handled analytically
    const float* W_attn = (const float*)d_in[2];
    const float* b_attn = (const float*)d_in[3];
    const float* W_proj = (const float*)d_in[4];
    const float* b_proj = (const float*)d_in[5];
    float* out = (float*)d_out;

    __nv_bfloat16 *xh, *xl, *wah, *wal, *wph, *wpl, *qh, *ql, *ah, *al;
    cudaGetSymbolAddress((void**)&xh, g_xh);   cudaGetSymbolAddress((void**)&xl, g_xl);
    cudaGetSymbolAddress((void**)&wah, g_wah); cudaGetSymbolAddress((void**)&wal, g_wal);
    cudaGetSymbolAddress((void**)&wph, g_wph); cudaGetSymbolAddress((void**)&wpl, g_wpl);
    cudaGetSymbolAddress((void**)&qh, g_qh);   cudaGetSymbolAddress((void**)&ql, g_ql);
    cudaGetSymbolAddress((void**)&ah, g_ah);   cudaGetSymbolAddress((void**)&al, g_al);

    static bool attr_done = false;
    if (!attr_done) {
        cudaFuncSetAttribute(mma_gemm<true>,  cudaFuncAttributeMaxDynamicSharedMemorySize, GEMM_SMEM);
        cudaFuncSetAttribute(mma_gemm<false>, cudaFuncAttributeMaxDynamicSharedMemorySize, GEMM_SMEM);
        cudaFuncSetAttribute(attn_mma, cudaFuncAttributeMaxDynamicSharedMemorySize, AT_SMEM);
        attr_done = true;
    }

    // pre-pass
    int n4x = SLEN * DM / 4;
    split_kernel<<<(n4x + 255) / 256, 256>>>((const float4*)x, (uint2*)xh, (uint2*)xl, n4x);
    tsplit_kernel<<<dim3(3 * DM / 32, DM / 32), dim3(32, 8)>>>(W_attn, wah, wal, DM, 3 * DM);
    tsplit_kernel<<<dim3(DM / 32, DM / 32), dim3(32, 8)>>>(W_proj, wph, wpl, DM, DM);

    // 1) QKV projection -> bf16 split qkv
    mma_gemm<false><<<dim3(3 * DM / 128, SLEN / 128), 256, GEMM_SMEM>>>(
        xh, xl, wah, wal, b_attn, nullptr, qh, ql, SLEN, 3 * DM, DM);

    // 2) tensor-core flash attention -> bf16 split output
    attn_mma<<<dim3(32, 16), 256, AT_SMEM>>>(qh, ql, ah, al);

    // 3) output projection -> fp32
    mma_gemm<true><<<dim3(DM / 128, SLEN / 128), 256, GEMM_SMEM>>>(
        ah, al, wph, wpl, b_proj, out, nullptr, nullptr, SLEN, DM, DM);
}

// round 16
// speedup vs baseline: 1.1069x; 1.0817x over previous
#include <cuda_runtime.h>
#include <cuda_bf16.h>
#include <cstdint>

#define SLEN 4096
#define DM   1024
#define NH   16
#define DH   64
#define QKV_LD (3*DM)

// ---------------- device-global scratch (no allocs allowed) ----------------
__device__ __nv_bfloat16 g_xh[(size_t)SLEN * DM], g_xl[(size_t)SLEN * DM];     // x split [S,K]
__device__ __nv_bfloat16 g_wah[(size_t)3*DM*DM],  g_wal[(size_t)3*DM*DM];      // W_attn^T split [N,K]
__device__ __nv_bfloat16 g_wph[(size_t)DM*DM],    g_wpl[(size_t)DM*DM];        // W_proj^T split [N,K]
__device__ __nv_bfloat16 g_qh[(size_t)SLEN * QKV_LD], g_ql[(size_t)SLEN * QKV_LD]; // qkv split
__device__ __nv_bfloat16 g_ah[(size_t)SLEN * DM], g_al[(size_t)SLEN * DM];     // attn out split

// ---------------- helpers ----------------
__device__ __forceinline__ uint32_t smem_u32(const void* p) {
    uint32_t a;
    asm("{ .reg .u64 t; cvta.to.shared.u64 t, %1; cvt.u32.u64 %0, t; }" : "=r"(a) : "l"(p));
    return a;
}
__device__ __forceinline__ void cp16(uint32_t s, const void* g) {
    asm volatile("cp.async.cg.shared.global [%0], [%1], 16;" :: "r"(s), "l"(g));
}
__device__ __forceinline__ void ldsm4(uint32_t a, uint32_t r[4]) {
    asm volatile("ldmatrix.sync.aligned.m8n8.x4.shared.b16 {%0,%1,%2,%3}, [%4];"
                 : "=r"(r[0]), "=r"(r[1]), "=r"(r[2]), "=r"(r[3]) : "r"(a));
}
__device__ __forceinline__ void ldsm4t(uint32_t a, uint32_t r[4]) {
    asm volatile("ldmatrix.sync.aligned.m8n8.x4.trans.shared.b16 {%0,%1,%2,%3}, [%4];"
                 : "=r"(r[0]), "=r"(r[1]), "=r"(r[2]), "=r"(r[3]) : "r"(a));
}
__device__ __forceinline__ void mma16816(float c[4], const uint32_t a[4], uint32_t b0, uint32_t b1) {
    asm volatile("mma.sync.aligned.m16n8k16.row.col.f32.bf16.bf16.f32 "
                 "{%0,%1,%2,%3}, {%4,%5,%6,%7}, {%8,%9}, {%0,%1,%2,%3};"
                 : "+f"(c[0]), "+f"(c[1]), "+f"(c[2]), "+f"(c[3])
                 : "r"(a[0]), "r"(a[1]), "r"(a[2]), "r"(a[3]), "r"(b0), "r"(b1));
}
// pack (a->low, b->high) as bf16x2
__device__ __forceinline__ uint32_t pkf(float a, float b) {
    uint32_t r;
    asm("cvt.rn.bf16x2.f32 %0, %1, %2;" : "=r"(r) : "f"(b), "f"(a));
    return r;
}
__device__ __forceinline__ float lowf(uint32_t x)  { return __uint_as_float(x << 16); }
__device__ __forceinline__ float highf(uint32_t x) { return __uint_as_float(x & 0xFFFF0000u); }

// fast exp2 on the FMA pipe (t <= 0), rel err ~1.5e-5
__device__ __forceinline__ float fexp2(float t) {
    t = fmaxf(t, -126.f);
    float fi = floorf(t);
    float f = t - fi;
    float p = 1.53998e-4f;
    p = fmaf(p, f, 1.33336e-3f);
    p = fmaf(p, f, 9.61813e-3f);
    p = fmaf(p, f, 5.55041e-2f);
    p = fmaf(p, f, 2.40227e-1f);
    p = fmaf(p, f, 6.93147e-1f);
    p = fmaf(p, f, 1.0f);
    return p * __int_as_float(((int)fi + 127) << 23);
}

// ---------------- pre-pass: fp32 -> bf16 hi/lo split ----------------
__global__ void split_kernel(const float4* __restrict__ in, uint2* __restrict__ hi,
                             uint2* __restrict__ lo, int n4)
{
    int i = blockIdx.x * 256 + threadIdx.x;
    if (i >= n4) return;
    float4 v = in[i];
    uint32_t h01 = pkf(v.x, v.y), h23 = pkf(v.z, v.w);
    uint32_t l01 = pkf(v.x - lowf(h01), v.y - highf(h01));
    uint32_t l23 = pkf(v.z - lowf(h23), v.w - highf(h23));
    hi[i] = make_uint2(h01, h23);
    lo[i] = make_uint2(l01, l23);
}

// ---------------- pre-pass: transpose + split  W[K,N] -> T[N,K] hi/lo ----------------
__global__ void tsplit_kernel(const float* __restrict__ W, __nv_bfloat16* __restrict__ Th,
                              __nv_bfloat16* __restrict__ Tl, int K, int N)
{
    __shared__ float t[32][33];
    int bx = blockIdx.x, by = blockIdx.y;
    int x = bx * 32 + threadIdx.x;
#pragma unroll
    for (int i = 0; i < 32; i += 8)
        t[threadIdx.y + i][threadIdx.x] = W[(size_t)(by * 32 + threadIdx.y + i) * N + x];
    __syncthreads();
    int kx = by * 32 + threadIdx.x;
#pragma unroll
    for (int i = 0; i < 32; i += 8) {
        float v = t[threadIdx.x][threadIdx.y + i];
        __nv_bfloat16 h = __float2bfloat16(v);
        size_t o = (size_t)(bx * 32 + threadIdx.y + i) * K + kx;
        Th[o] = h;
        Tl[o] = __float2bfloat16(v - __bfloat162float(h));
    }
}

// ---------------------------------------------------------------------------
// mma.sync GEMM: C = (Ah+Al)[M,K] @ (Bh+Bl)[N,K]^T + bias
// R10 compute shape: 256 threads / 8 warps (4x2), warp tile 32x64 (1:4
// ldsm:mma), K-chunks of 64 (128B rows, XOR-8 swizzle). Variable under test:
// 3-stage cp.async pipeline with ONE __syncthreads per chunk; prefetch j+2
// issued before compute(j). 192KB smem, 1 CTA/SM.
// OUT_F32 selects fp32 vs bf16 hi/lo split epilogue (compile-time).
// ---------------------------------------------------------------------------
#define KC        64
#define TILE_B    16384                 // 128 rows * 128 bytes
#define STG_B     (4 * TILE_B)          // Ah, Al, Bh, Bl per stage
#define GEMM_SMEM (3 * STG_B)           // 196608 B

template<bool OUT_F32>
__global__ __launch_bounds__(256, 1)
void mma_gemm(const __nv_bfloat16* __restrict__ Ah, const __nv_bfloat16* __restrict__ Al,
              const __nv_bfloat16* __restrict__ Bh, const __nv_bfloat16* __restrict__ Bl,
              const float* __restrict__ bias, float* __restrict__ Cf,
              __nv_bfloat16* __restrict__ Ch, __nv_bfloat16* __restrict__ Cl,
              int M, int N, int K)
{
    extern __shared__ char smem[];
    uint32_t sb = smem_u32(smem);
    int tid = threadIdx.x;
    int l   = tid & 31;
    int wid = tid >> 5;
    int bn = blockIdx.x, bm = blockIdx.y;

    // ---- loader mapping (R10): 32 row-groups x 8 sixteen-byte cols ----
    int rb  = tid >> 3;                               // 0..31
    int c16 = tid & 7;                                // 16B col
    uint32_t sw = (uint32_t)((c16 ^ (rb & 7)) << 4);  // row-invariant (rows step by 32)

    const __nv_bfloat16* A0h = Ah + (size_t)(bm * 128 + rb) * K + c16 * 8;
    const __nv_bfloat16* A0l = Al + (size_t)(bm * 128 + rb) * K + c16 * 8;
    const __nv_bfloat16* B0h = Bh + (size_t)(bn * 128 + rb) * K + c16 * 8;
    const __nv_bfloat16* B0l = Bl + (size_t)(bn * 128 + rb) * K + c16 * 8;

    auto load_chunk = [&](int c, int st) {
        uint32_t s0 = sb + (uint32_t)st * STG_B;
        size_t gofs = (size_t)c * KC;
#pragma unroll
        for (int p = 0; p < 4; p++) {
            uint32_t so = (uint32_t)(rb + 32 * p) * 128 + sw;
            size_t go = (size_t)(32 * p) * K + gofs;
            cp16(s0 + so,              A0h + go);
            cp16(s0 + TILE_B + so,     A0l + go);
            cp16(s0 + 2 * TILE_B + so, B0h + go);
            cp16(s0 + 3 * TILE_B + so, B0l + go);
        }
        asm volatile("cp.async.commit_group;" ::: "memory");
    };

    // ---- compute mapping (R10): warp (wm, wn) owns 32x64 ----
    int wm = wid >> 1, wn = wid & 1;
    int m0 = wm * 32, n0 = wn * 64;

    int rowA_lane = l & 15;
    int k16A      = l >> 4;
    int rowB_lane = (l & 7) + 8 * (l >> 4);
    int k16B      = (l >> 3) & 1;

    float acc[2][8][4];
#pragma unroll
    for (int mf = 0; mf < 2; mf++)
#pragma unroll
        for (int nf = 0; nf < 8; nf++)
#pragma unroll
            for (int q = 0; q < 4; q++) acc[mf][nf][q] = 0.f;

    auto compute = [&](int st) {
        uint32_t base = sb + (uint32_t)st * STG_B;
#pragma unroll
        for (int ks = 0; ks < 4; ks++) {
            uint32_t ahf[2][4], alf[2][4];
#pragma unroll
            for (int mf = 0; mf < 2; mf++) {
                uint32_t row = (uint32_t)(m0 + mf * 16 + rowA_lane);
                uint32_t off = row * 128 + (uint32_t)(((ks * 2 + k16A) ^ (row & 7)) << 4);
                ldsm4(base + off,          ahf[mf]);
                ldsm4(base + TILE_B + off, alf[mf]);
            }
#pragma unroll
            for (int nfp = 0; nfp < 4; nfp++) {
                uint32_t row = (uint32_t)(n0 + nfp * 16 + rowB_lane);
                uint32_t off = row * 128 + (uint32_t)(((ks * 2 + k16B) ^ (row & 7)) << 4);
                uint32_t bhf[4], blf[4];
                ldsm4(base + 2 * TILE_B + off, bhf);
                ldsm4(base + 3 * TILE_B + off, blf);
#pragma unroll
                for (int mf = 0; mf < 2; mf++)
#pragma unroll
                    for (int nf = 0; nf < 2; nf++) {
                        float* c = acc[mf][nfp * 2 + nf];
                        mma16816(c, ahf[mf], bhf[2 * nf], bhf[2 * nf + 1]);
                        mma16816(c, ahf[mf], blf[2 * nf], blf[2 * nf + 1]);
                        mma16816(c, alf[mf], bhf[2 * nf], bhf[2 * nf + 1]);
                    }
            }
        }
    };

    int NCH = K / KC;                 // 16
    load_chunk(0, 0);
    load_chunk(1, 1);
    for (int j = 0; j < NCH; j++) {
        if (j < NCH - 1)
            asm volatile("cp.async.wait_group 1;" ::: "memory");
        else
            asm volatile("cp.async.wait_group 0;" ::: "memory");
        __syncthreads();              // orders compute(j-1) before the overwrite below
        if (j + 2 < NCH) load_chunk(j + 2, (j + 2) % 3);
        compute(j % 3);
    }

    // ---- epilogue ----
#pragma unroll
    for (int mf = 0; mf < 2; mf++) {
        int r0 = bm * 128 + m0 + mf * 16 + (l >> 2);
#pragma unroll
        for (int nfp = 0; nfp < 4; nfp++) {
#pragma unroll
            for (int nf = 0; nf < 2; nf++) {
                int col = bn * 128 + n0 + nfp * 16 + nf * 8 + 2 * (l & 3);
                float2 bv = *(const float2*)&bias[col];
                const float* c = acc[mf][nfp * 2 + nf];
                float a0 = c[0] + bv.x, a1 = c[1] + bv.y;
                float a2 = c[2] + bv.x, a3 = c[3] + bv.y;
                if (OUT_F32) {
                    *(float2*)&Cf[(size_t)r0 * N + col]       = make_float2(a0, a1);
                    *(float2*)&Cf[(size_t)(r0 + 8) * N + col] = make_float2(a2, a3);
                } else {
                    uint32_t h0 = pkf(a0, a1), h1 = pkf(a2, a3);
                    uint32_t l0 = pkf(a0 - lowf(h0), a1 - highf(h0));
                    uint32_t l1 = pkf(a2 - lowf(h1), a3 - highf(h1));
                    *(uint32_t*)&Ch[(size_t)r0 * N + col]       = h0;
                    *(uint32_t*)&Cl[(size_t)r0 * N + col]       = l0;
                    *(uint32_t*)&Ch[(size_t)(r0 + 8) * N + col] = h1;
                    *(uint32_t*)&Cl[(size_t)(r0 + 8) * N + col] = l1;
                }
            }
        }
    }
}

// ---------------------------------------------------------------------------
// mma.sync flash attention, split bf16, causal — unchanged (verified R10).
// CTA = 128 queries x 1 head, 8 warps x 16 q-rows, key blocks of 128.
// ---------------------------------------------------------------------------
#define AT_SMEM (32768 + 2 * 65536)

__global__ __launch_bounds__(256, 1)
void attn_mma(const __nv_bfloat16* __restrict__ qkh, const __nv_bfloat16* __restrict__ qkl,
              __nv_bfloat16* __restrict__ oh, __nv_bfloat16* __restrict__ ol)
{
    extern __shared__ char smem[];
    uint32_t sb = smem_u32(smem);
    const int tid = threadIdx.x;
    const int l = tid & 31;
    const int w = tid >> 5;
    int flat = (int)blockIdx.y * 32 + (int)blockIdx.x;
    const int h  = flat & 15;
    const int qb = 31 - (flat >> 4);
    const size_t hofs = (size_t)h * DH;

    {
        int rb = tid >> 2, c2 = tid & 3;
#pragma unroll
        for (int rh = 0; rh < 2; rh++)
#pragma unroll
            for (int cc = 0; cc < 2; cc++) {
                int row = rb + rh * 64, c16 = c2 + cc * 4;
                uint32_t so = (uint32_t)row * 128 + (uint32_t)((c16 ^ (row & 7)) << 4);
                size_t go = (size_t)(qb * 128 + row) * QKV_LD + hofs + c16 * 8;
                cp16(sb + so,         qkh + go);
                cp16(sb + 16384 + so, qkl + go);
            }
        asm volatile("cp.async.commit_group;" ::: "memory");
    }
    auto load_kv = [&](int kb, int st) {
        uint32_t s0 = sb + 32768 + st * 65536;
        int rb = tid >> 2, c2 = tid & 3;
#pragma unroll
        for (int rh = 0; rh < 2; rh++)
#pragma unroll
            for (int cc = 0; cc < 2; cc++) {
                int row = rb + rh * 64, c16 = c2 + cc * 4;
                uint32_t so = (uint32_t)row * 128 + (uint32_t)((c16 ^ (row & 7)) << 4);
                size_t gk = (size_t)(kb * 128 + row) * QKV_LD + DM + hofs + c16 * 8;
                size_t gv = gk + DM;
                cp16(s0 + so,         qkh + gk);
                cp16(s0 + 16384 + so, qkl + gk);
                cp16(s0 + 32768 + so, qkh + gv);
                cp16(s0 + 49152 + so, qkl + gv);
            }
        asm volatile("cp.async.commit_group;" ::: "memory");
    };
    load_kv(0, 0);

    const int g    = l >> 2;
    const int rowA = l & 15, kA = l >> 4;
    const int rowB = (l & 7) + 8 * (l >> 4), kB = (l >> 3) & 1;
    const int rowV = (l & 7) + 8 * ((l >> 3) & 1), cV = l >> 4;
    const float CE = 0.125f * 1.44269504f;

    uint32_t qfh[4][4], qfl[4][4];
    float O[8][4];
    float mrow0 = -1e30f, mrow1 = -1e30f, ls0 = 0.f, ls1 = 0.f;
#pragma unroll
    for (int i = 0; i < 8; i++)
#pragma unroll
        for (int q = 0; q < 4; q++) O[i][q] = 0.f;

    for (int j = 0; j <= qb; j++) {
        if (j < qb) {
            load_kv(j + 1, (j + 1) & 1);
            asm volatile("cp.async.wait_group 1;" ::: "memory");
        } else {
            asm volatile("cp.async.wait_group 0;" ::: "memory");
        }
        __syncthreads();
        if (j == 0) {
#pragma unroll
            for (int t = 0; t < 4; t++) {
                int row = w * 16 + rowA;
                uint32_t off = (uint32_t)row * 128 + (uint32_t)((((t * 2 + kA) ^ (row & 7))) << 4);
                ldsm4(sb + off,         qfh[t]);
                ldsm4(sb + 16384 + off, qfl[t]);
            }
        }
        uint32_t base = sb + 32768 + (uint32_t)(j & 1) * 65536;

        float S[16][4];
#pragma unroll
        for (int a = 0; a < 16; a++)
#pragma unroll
            for (int b = 0; b < 4; b++) S[a][b] = 0.f;

#pragma unroll
        for (int np = 0; np < 8; np++) {
#pragma unroll
            for (int t = 0; t < 4; t++) {
                int row = np * 16 + rowB;
                uint32_t off = (uint32_t)row * 128 + (uint32_t)((((t * 2 + kB) ^ (row & 7))) << 4);
                uint32_t kh[4], kl[4];
                ldsm4(base + off,         kh);
                ldsm4(base + 16384 + off, kl);
                mma16816(S[2 * np],     qfh[t], kh[0], kh[1]);
                mma16816(S[2 * np],     qfh[t], kl[0], kl[1]);
                mma16816(S[2 * np],     qfl[t], kh[0], kh[1]);
                mma16816(S[2 * np + 1], qfh[t], kh[2], kh[3]);
                mma16816(S[2 * np + 1], qfh[t], kl[2], kl[3]);
                mma16816(S[2 * np + 1], qfl[t], kh[2], kh[3]);
            }
        }

        if (j == qb) {
            int r0 = w * 16 + g;
#pragma unroll
            for (int nf = 0; nf < 16; nf++) {
                int c0 = nf * 8 + 2 * (l & 3);
                if (c0     > r0)     S[nf][0] = -1e30f;
                if (c0 + 1 > r0)     S[nf][1] = -1e30f;
                if (c0     > r0 + 8) S[nf][2] = -1e30f;
                if (c0 + 1 > r0 + 8) S[nf][3] = -1e30f;
            }
        }

        float mx0 = -1e30f, mx1 = -1e30f;
#pragma unroll
        for (int nf = 0; nf < 16; nf++) {
            mx0 = fmaxf(mx0, fmaxf(S[nf][0], S[nf][1]));
            mx1 = fmaxf(mx1, fmaxf(S[nf][2], S[nf][3]));
        }
        mx0 = fmaxf(mx0, __shfl_xor_sync(0xffffffffu, mx0, 1));
        mx0 = fmaxf(mx0, __shfl_xor_sync(0xffffffffu, mx0, 2));
        mx1 = fmaxf(mx1, __shfl_xor_sync(0xffffffffu, mx1, 1));
        mx1 = fmaxf(mx1, __shfl_xor_sync(0xffffffffu, mx1, 2));
        float mn0 = fmaxf(mrow0, mx0), mn1 = fmaxf(mrow1, mx1);
        float cr0 = fexp2((mrow0 - mn0) * CE), cr1 = fexp2((mrow1 - mn1) * CE);
        mrow0 = mn0; mrow1 = mn1;
        float nm0 = mn0 * CE, nm1 = mn1 * CE;
#pragma unroll
        for (int nf = 0; nf < 8; nf++) {
            O[nf][0] *= cr0; O[nf][1] *= cr0;
            O[nf][2] *= cr1; O[nf][3] *= cr1;
        }
        float s0 = 0.f, s1 = 0.f;
#pragma unroll
        for (int t = 0; t < 8; t++) {
            float p00 = fexp2(fmaf(S[2*t][0],   CE, -nm0));
            float p01 = fexp2(fmaf(S[2*t][1],   CE, -nm0));
            float p02 = fexp2(fmaf(S[2*t][2],   CE, -nm1));
            float p03 = fexp2(fmaf(S[2*t][3],   CE, -nm1));
            float p10 = fexp2(fmaf(S[2*t+1][0], CE, -nm0));
            float p11 = fexp2(fmaf(S[2*t+1][1], CE, -nm0));
            float p12 = fexp2(fmaf(S[2*t+1][2], CE, -nm1));
            float p13 = fexp2(fmaf(S[2*t+1][3], CE, -nm1));
            s0 += (p00 + p01) + (p10 + p11);
            s1 += (p02 + p03) + (p12 + p13);
            uint32_t h0 = pkf(p00, p01), h1 = pkf(p02, p03);
            uint32_t h2 = pkf(p10, p11), h3 = pkf(p12, p13);
            uint32_t e0 = pkf(p00 - lowf(h0), p01 - highf(h0));
            uint32_t e1 = pkf(p02 - lowf(h1), p03 - highf(h1));
            uint32_t e2 = pkf(p10 - lowf(h2), p11 - highf(h2));
            uint32_t e3 = pkf(p12 - lowf(h3), p13 - highf(h3));
            S[2*t][0]   = __uint_as_float(h0);
            S[2*t][1]   = __uint_as_float(h1);
            S[2*t][2]   = __uint_as_float(h2);
            S[2*t][3]   = __uint_as_float(h3);
            S[2*t+1][0] = __uint_as_float(e0);
            S[2*t+1][1] = __uint_as_float(e1);
            S[2*t+1][2] = __uint_as_float(e2);
            S[2*t+1][3] = __uint_as_float(e3);
        }
        ls0 = ls0 * cr0 + s0;
        ls1 = ls1 * cr1 + s1;

#pragma unroll
        for (int t = 0; t < 8; t++) {
            uint32_t Ahf[4] = {__float_as_uint(S[2*t][0]),   __float_as_uint(S[2*t][1]),
                               __float_as_uint(S[2*t][2]),   __float_as_uint(S[2*t][3])};
            uint32_t Alf[4] = {__float_as_uint(S[2*t+1][0]), __float_as_uint(S[2*t+1][1]),
                               __float_as_uint(S[2*t+1][2]), __float_as_uint(S[2*t+1][3])};
#pragma unroll
            for (int vp = 0; vp < 4; vp++) {
                int row = t * 16 + rowV;
                uint32_t off = (uint32_t)row * 128 + (uint32_t)((((vp * 2 + cV) ^ (row & 7))) << 4);
                uint32_t vh[4], vl[4];
                ldsm4t(base + 32768 + off, vh);
                ldsm4t(base + 49152 + off, vl);
                mma16816(O[2 * vp],     Ahf, vh[0], vh[1]);
                mma16816(O[2 * vp],     Ahf, vl[0], vl[1]);
                mma16816(O[2 * vp],     Alf, vh[0], vh[1]);
                mma16816(O[2 * vp + 1], Ahf, vh[2], vh[3]);
                mma16816(O[2 * vp + 1], Ahf, vl[2], vl[3]);
                mma16816(O[2 * vp + 1], Alf, vh[2], vh[3]);
            }
        }
        __syncthreads();
    }

    ls0 += __shfl_xor_sync(0xffffffffu, ls0, 1);
    ls0 += __shfl_xor_sync(0xffffffffu, ls0, 2);
    ls1 += __shfl_xor_sync(0xffffffffu, ls1, 1);
    ls1 += __shfl_xor_sync(0xffffffffu, ls1, 2);
    float inv0 = 1.f / ls0, inv1 = 1.f / ls1;
    int r0 = qb * 128 + w * 16 + g;
#pragma unroll
    for (int nf = 0; nf < 8; nf++) {
        int col = nf * 8 + 2 * (l & 3);
        size_t o0 = (size_t)r0 * DM + hofs + col;
        size_t o1 = (size_t)(r0 + 8) * DM + hofs + col;
        float a0 = O[nf][0] * inv0, a1 = O[nf][1] * inv0;
        float a2 = O[nf][2] * inv1, a3 = O[nf][3] * inv1;
        uint32_t h0 = pkf(a0, a1), h1 = pkf(a2, a3);
        *(uint32_t*)&oh[o0] = h0;
        *(uint32_t*)&ol[o0] = pkf(a0 - lowf(h0), a1 - highf(h0));
        *(uint32_t*)&oh[o1] = h1;
        *(uint32_t*)&ol[o1] = pkf(a2 - lowf(h1), a3 - highf(h1));
    }
}

// ---------------------------------------------------------------------------
extern "C" void kernel_launch(void* const* d_in, const int* in_sizes, int n_in,
                              void* d_out, int out_size)
{
    const float* x      = (const float*)d_in[0];
    // d_in[1] = additive causal mask — exactly causal, handled analytically
    const float* W_attn = (const float*)d_in[2];
    const float* b_attn = (const float*)d_in[3];
    const float* W_proj = (const float*)d_in[4];
    const float* b_proj = (const float*)d_in[5];
    float* out = (float*)d_out;

    __nv_bfloat16 *xh, *xl, *wah, *wal, *wph, *wpl, *qh, *ql, *ah, *al;
    cudaGetSymbolAddress((void**)&xh, g_xh);   cudaGetSymbolAddress((void**)&xl, g_xl);
    cudaGetSymbolAddress((void**)&wah, g_wah); cudaGetSymbolAddress((void**)&wal, g_wal);
    cudaGetSymbolAddress((void**)&wph, g_wph); cudaGetSymbolAddress((void**)&wpl, g_wpl);
    cudaGetSymbolAddress((void**)&qh, g_qh);   cudaGetSymbolAddress((void**)&ql, g_ql);
    cudaGetSymbolAddress((void**)&ah, g_ah);   cudaGetSymbolAddress((void**)&al, g_al);

    static bool attr_done = false;
    if (!attr_done) {
        cudaFuncSetAttribute(mma_gemm<true>,  cudaFuncAttributeMaxDynamicSharedMemorySize, GEMM_SMEM);
        cudaFuncSetAttribute(mma_gemm<false>, cudaFuncAttributeMaxDynamicSharedMemorySize, GEMM_SMEM);
        cudaFuncSetAttribute(attn_mma, cudaFuncAttributeMaxDynamicSharedMemorySize, AT_SMEM);
        attr_done = true;
    }

    // pre-pass
    int n4x = SLEN * DM / 4;
    split_kernel<<<(n4x + 255) / 256, 256>>>((const float4*)x, (uint2*)xh, (uint2*)xl, n4x);
    tsplit_kernel<<<dim3(3 * DM / 32, DM / 32), dim3(32, 8)>>>(W_attn, wah, wal, DM, 3 * DM);
    tsplit_kernel<<<dim3(DM / 32, DM / 32), dim3(32, 8)>>>(W_proj, wph, wpl, DM, DM);

    // 1) QKV projection -> bf16 split qkv
    mma_gemm<false><<<dim3(3 * DM / 128, SLEN / 128), 256, GEMM_SMEM>>>(
        xh, xl, wah, wal, b_attn, nullptr, qh, ql, SLEN, 3 * DM, DM);

    // 2) tensor-core flash attention -> bf16 split output
    attn_mma<<<dim3(32, 16), 256, AT_SMEM>>>(qh, ql, ah, al);

    // 3) output projection -> fp32
    mma_gemm<true><<<dim3(DM / 128, SLEN / 128), 256, GEMM_SMEM>>>(
        ah, al, wph, wpl, b_proj, out, nullptr, nullptr, SLEN, DM, DM);
}

// round 17
// speedup vs baseline: 1.4545x; 1.3140x over previous
#include <cuda_runtime.h>
#include <cuda_fp16.h>
#include <cstdint>

#define SLEN 4096
#define DM   1024
#define NH   16
#define DH   64
#define QKV_LD (3*DM)

// ---------------- device-global scratch (no allocs allowed) ----------------
__device__ __half g_xh[(size_t)SLEN * DM];                                   // x fp16 (single)
__device__ __half g_wah[(size_t)3*DM*DM], g_wal[(size_t)3*DM*DM];            // W_attn^T fp16 split
__device__ __half g_wph[(size_t)DM*DM],   g_wpl[(size_t)DM*DM];              // W_proj^T fp16 split
__device__ __half g_qh[(size_t)SLEN * QKV_LD], g_ql[(size_t)SLEN * QKV_LD];  // qkv fp16 split
__device__ __half g_ah[(size_t)SLEN * DM];                                   // attn out fp16 (single)

// ---------------- helpers ----------------
__device__ __forceinline__ uint32_t smem_u32(const void* p) {
    uint32_t a;
    asm("{ .reg .u64 t; cvta.to.shared.u64 t, %1; cvt.u32.u64 %0, t; }" : "=r"(a) : "l"(p));
    return a;
}
__device__ __forceinline__ void cp16(uint32_t s, const void* g) {
    asm volatile("cp.async.cg.shared.global [%0], [%1], 16;" :: "r"(s), "l"(g));
}
__device__ __forceinline__ void ldsm4(uint32_t a, uint32_t r[4]) {
    asm volatile("ldmatrix.sync.aligned.m8n8.x4.shared.b16 {%0,%1,%2,%3}, [%4];"
                 : "=r"(r[0]), "=r"(r[1]), "=r"(r[2]), "=r"(r[3]) : "r"(a));
}
__device__ __forceinline__ void ldsm4t(uint32_t a, uint32_t r[4]) {
    asm volatile("ldmatrix.sync.aligned.m8n8.x4.trans.shared.b16 {%0,%1,%2,%3}, [%4];"
                 : "=r"(r[0]), "=r"(r[1]), "=r"(r[2]), "=r"(r[3]) : "r"(a));
}
__device__ __forceinline__ void mma16816(float c[4], const uint32_t a[4], uint32_t b0, uint32_t b1) {
    asm volatile("mma.sync.aligned.m16n8k16.row.col.f32.f16.f16.f32 "
                 "{%0,%1,%2,%3}, {%4,%5,%6,%7}, {%8,%9}, {%0,%1,%2,%3};"
                 : "+f"(c[0]), "+f"(c[1]), "+f"(c[2]), "+f"(c[3])
                 : "r"(a[0]), "r"(a[1]), "r"(a[2]), "r"(a[3]), "r"(b0), "r"(b1));
}
// pack (a->low half, b->high half) as f16x2
__device__ __forceinline__ uint32_t pkh(float a, float b) {
    uint32_t r;
    asm("cvt.rn.f16x2.f32 %0, %1, %2;" : "=r"(r) : "f"(b), "f"(a));
    return r;
}
__device__ __forceinline__ float lowh(uint32_t x) {
    return __half2float(__ushort_as_half((unsigned short)(x & 0xFFFFu)));
}
__device__ __forceinline__ float highh(uint32_t x) {
    return __half2float(__ushort_as_half((unsigned short)(x >> 16)));
}

// fast exp2 on the FMA pipe (t <= 0), rel err ~1.5e-5
__device__ __forceinline__ float fexp2(float t) {
    t = fmaxf(t, -126.f);
    float fi = floorf(t);
    float f = t - fi;
    float p = 1.53998e-4f;
    p = fmaf(p, f, 1.33336e-3f);
    p = fmaf(p, f, 9.61813e-3f);
    p = fmaf(p, f, 5.55041e-2f);
    p = fmaf(p, f, 2.40227e-1f);
    p = fmaf(p, f, 6.93147e-1f);
    p = fmaf(p, f, 1.0f);
    return p * __int_as_float(((int)fi + 127) << 23);
}

// ---------------- pre-pass: fp32 -> fp16 convert (single) ----------------
__global__ void cvt_h_kernel(const float4* __restrict__ in, uint2* __restrict__ out, int n4)
{
    int i = blockIdx.x * 256 + threadIdx.x;
    if (i >= n4) return;
    float4 v = in[i];
    out[i] = make_uint2(pkh(v.x, v.y), pkh(v.z, v.w));
}

// ---------------- pre-pass: transpose + fp16 hi/lo split  W[K,N] -> T[N,K] ----------------
__global__ void tsplit_kernel(const float* __restrict__ W, __half* __restrict__ Th,
                              __half* __restrict__ Tl, int K, int N)
{
    __shared__ float t[32][33];
    int bx = blockIdx.x, by = blockIdx.y;
    int x = bx * 32 + threadIdx.x;
#pragma unroll
    for (int i = 0; i < 32; i += 8)
        t[threadIdx.y + i][threadIdx.x] = W[(size_t)(by * 32 + threadIdx.y + i) * N + x];
    __syncthreads();
    int kx = by * 32 + threadIdx.x;
#pragma unroll
    for (int i = 0; i < 32; i += 8) {
        float v = t[threadIdx.x][threadIdx.y + i];
        __half h = __float2half_rn(v);
        size_t o = (size_t)(bx * 32 + threadIdx.y + i) * K + kx;
        Th[o] = h;
        Tl[o] = __float2half_rn(v - __half2float(h));
    }
}

// ---------------------------------------------------------------------------
// mma.sync GEMM (fp16, 2-term): C = A[M,K] @ (Bh+Bl)[N,K]^T + bias
// 256 threads / 8 warps (4x2), warp tile 32x64, K-chunks of 64 (128B rows,
// XOR-8 swizzle), 3-stage cp.async pipeline, one __syncthreads per chunk.
// OUT_F32 selects fp32 vs fp16 hi/lo split epilogue (compile-time).
// ---------------------------------------------------------------------------
#define KC        64
#define TILE_B    16384                 // 128 rows * 128 bytes (64 fp16)
#define STG_B     (3 * TILE_B)          // A, Bh, Bl per stage
#define GEMM_SMEM (3 * STG_B)           // 147456 B

template<bool OUT_F32>
__global__ __launch_bounds__(256, 1)
void mma_gemm(const __half* __restrict__ A, const __half* __restrict__ Bh,
              const __half* __restrict__ Bl,
              const float* __restrict__ bias, float* __restrict__ Cf,
              __half* __restrict__ Ch, __half* __restrict__ Cl,
              int M, int N, int K)
{
    extern __shared__ char smem[];
    uint32_t sb = smem_u32(smem);
    int tid = threadIdx.x;
    int l   = tid & 31;
    int wid = tid >> 5;
    int bn = blockIdx.x, bm = blockIdx.y;

    // ---- loader mapping: 32 row-groups x 8 sixteen-byte cols ----
    int rb  = tid >> 3;                               // 0..31
    int c16 = tid & 7;                                // 16B col
    uint32_t sw = (uint32_t)((c16 ^ (rb & 7)) << 4);  // row-invariant (rows step by 32)

    const __half* A0  = A  + (size_t)(bm * 128 + rb) * K + c16 * 8;
    const __half* B0h = Bh + (size_t)(bn * 128 + rb) * K + c16 * 8;
    const __half* B0l = Bl + (size_t)(bn * 128 + rb) * K + c16 * 8;

    auto load_chunk = [&](int c, int st) {
        uint32_t s0 = sb + (uint32_t)st * STG_B;
        size_t gofs = (size_t)c * KC;
#pragma unroll
        for (int p = 0; p < 4; p++) {
            uint32_t so = (uint32_t)(rb + 32 * p) * 128 + sw;
            size_t go = (size_t)(32 * p) * K + gofs;
            cp16(s0 + so,              A0  + go);
            cp16(s0 + TILE_B + so,     B0h + go);
            cp16(s0 + 2 * TILE_B + so, B0l + go);
        }
        asm volatile("cp.async.commit_group;" ::: "memory");
    };

    // ---- compute mapping: warp (wm, wn) owns 32x64 ----
    int wm = wid >> 1, wn = wid & 1;
    int m0 = wm * 32, n0 = wn * 64;

    int rowA_lane = l & 15;
    int k16A      = l >> 4;
    int rowB_lane = (l & 7) + 8 * (l >> 4);
    int k16B      = (l >> 3) & 1;

    float acc[2][8][4];
#pragma unroll
    for (int mf = 0; mf < 2; mf++)
#pragma unroll
        for (int nf = 0; nf < 8; nf++)
#pragma unroll
            for (int q = 0; q < 4; q++) acc[mf][nf][q] = 0.f;

    auto compute = [&](int st) {
        uint32_t base = sb + (uint32_t)st * STG_B;
#pragma unroll
        for (int ks = 0; ks < 4; ks++) {
            uint32_t af[2][4];
#pragma unroll
            for (int mf = 0; mf < 2; mf++) {
                uint32_t row = (uint32_t)(m0 + mf * 16 + rowA_lane);
                uint32_t off = row * 128 + (uint32_t)(((ks * 2 + k16A) ^ (row & 7)) << 4);
                ldsm4(base + off, af[mf]);
            }
#pragma unroll
            for (int nfp = 0; nfp < 4; nfp++) {
                uint32_t row = (uint32_t)(n0 + nfp * 16 + rowB_lane);
                uint32_t off = row * 128 + (uint32_t)(((ks * 2 + k16B) ^ (row & 7)) << 4);
                uint32_t bhf[4], blf[4];
                ldsm4(base + TILE_B + off,     bhf);
                ldsm4(base + 2 * TILE_B + off, blf);
#pragma unroll
                for (int mf = 0; mf < 2; mf++)
#pragma unroll
                    for (int nf = 0; nf < 2; nf++) {
                        float* c = acc[mf][nfp * 2 + nf];
                        mma16816(c, af[mf], bhf[2 * nf], bhf[2 * nf + 1]);
                        mma16816(c, af[mf], blf[2 * nf], blf[2 * nf + 1]);
                    }
            }
        }
    };

    int NCH = K / KC;                 // 16
    load_chunk(0, 0);
    load_chunk(1, 1);
    for (int j = 0; j < NCH; j++) {
        if (j < NCH - 1)
            asm volatile("cp.async.wait_group 1;" ::: "memory");
        else
            asm volatile("cp.async.wait_group 0;" ::: "memory");
        __syncthreads();              // orders compute(j-1) before the overwrite below
        if (j + 2 < NCH) load_chunk(j + 2, (j + 2) % 3);
        compute(j % 3);
    }

    // ---- epilogue ----
#pragma unroll
    for (int mf = 0; mf < 2; mf++) {
        int r0 = bm * 128 + m0 + mf * 16 + (l >> 2);
#pragma unroll
        for (int nfp = 0; nfp < 4; nfp++) {
#pragma unroll
            for (int nf = 0; nf < 2; nf++) {
                int col = bn * 128 + n0 + nfp * 16 + nf * 8 + 2 * (l & 3);
                float2 bv = *(const float2*)&bias[col];
                const float* c = acc[mf][nfp * 2 + nf];
                float a0 = c[0] + bv.x, a1 = c[1] + bv.y;
                float a2 = c[2] + bv.x, a3 = c[3] + bv.y;
                if (OUT_F32) {
                    *(float2*)&Cf[(size_t)r0 * N + col]       = make_float2(a0, a1);
                    *(float2*)&Cf[(size_t)(r0 + 8) * N + col] = make_float2(a2, a3);
                } else {
                    uint32_t h0 = pkh(a0, a1), h1 = pkh(a2, a3);
                    uint32_t l0 = pkh(a0 - lowh(h0), a1 - highh(h0));
                    uint32_t l1 = pkh(a2 - lowh(h1), a3 - highh(h1));
                    *(uint32_t*)&Ch[(size_t)r0 * N + col]       = h0;
                    *(uint32_t*)&Cl[(size_t)r0 * N + col]       = l0;
                    *(uint32_t*)&Ch[(size_t)(r0 + 8) * N + col] = h1;
                    *(uint32_t*)&Cl[(size_t)(r0 + 8) * N + col] = l1;
                }
            }
        }
    }
}

// ---------------------------------------------------------------------------
// mma.sync flash attention, fp16 2-term, causal.
// CTA = 128 queries x 1 head, 8 warps x 16 q-rows, key blocks of 128.
// Q single fp16 (16KB); KV stages {Kh,Kl,Vh,Vl} 64KB x2. P single fp16.
// Output single fp16 (feeds proj as A operand).
// ---------------------------------------------------------------------------
#define AT_SMEM (16384 + 2 * 65536)     // 147456 B

__global__ __launch_bounds__(256, 1)
void attn_mma(const __half* __restrict__ qkh, const __half* __restrict__ qkl,
              __half* __restrict__ oh)
{
    extern __shared__ char smem[];
    uint32_t sb = smem_u32(smem);
    const int tid = threadIdx.x;
    const int l = tid & 31;
    const int w = tid >> 5;
    int flat = (int)blockIdx.y * 32 + (int)blockIdx.x;
    const int h  = flat & 15;
    const int qb = 31 - (flat >> 4);
    const size_t hofs = (size_t)h * DH;

    // ---- Q tile load (hi only) ----
    {
        int rb = tid >> 2, c2 = tid & 3;
#pragma unroll
        for (int rh = 0; rh < 2; rh++)
#pragma unroll
            for (int cc = 0; cc < 2; cc++) {
                int row = rb + rh * 64, c16 = c2 + cc * 4;
                uint32_t so = (uint32_t)row * 128 + (uint32_t)((c16 ^ (row & 7)) << 4);
                size_t go = (size_t)(qb * 128 + row) * QKV_LD + hofs + c16 * 8;
                cp16(sb + so, qkh + go);
            }
        asm volatile("cp.async.commit_group;" ::: "memory");
    }
    auto load_kv = [&](int kb, int st) {
        uint32_t s0 = sb + 16384 + st * 65536;
        int rb = tid >> 2, c2 = tid & 3;
#pragma unroll
        for (int rh = 0; rh < 2; rh++)
#pragma unroll
            for (int cc = 0; cc < 2; cc++) {
                int row = rb + rh * 64, c16 = c2 + cc * 4;
                uint32_t so = (uint32_t)row * 128 + (uint32_t)((c16 ^ (row & 7)) << 4);
                size_t gk = (size_t)(kb * 128 + row) * QKV_LD + DM + hofs + c16 * 8;
                size_t gv = gk + DM;
                cp16(s0 + so,         qkh + gk);
                cp16(s0 + 16384 + so, qkl + gk);
                cp16(s0 + 32768 + so, qkh + gv);
                cp16(s0 + 49152 + so, qkl + gv);
            }
        asm volatile("cp.async.commit_group;" ::: "memory");
    };
    load_kv(0, 0);

    const int g    = l >> 2;
    const int rowA = l & 15, kA = l >> 4;
    const int rowB = (l & 7) + 8 * (l >> 4), kB = (l >> 3) & 1;
    const int rowV = (l & 7) + 8 * ((l >> 3) & 1), cV = l >> 4;
    const float CE = 0.125f * 1.44269504f;   // scale * log2(e)

    uint32_t qf[4][4];
    float O[8][4];
    float mrow0 = -1e30f, mrow1 = -1e30f, ls0 = 0.f, ls1 = 0.f;
#pragma unroll
    for (int i = 0; i < 8; i++)
#pragma unroll
        for (int q = 0; q < 4; q++) O[i][q] = 0.f;

    for (int j = 0; j <= qb; j++) {
        if (j < qb) {
            load_kv(j + 1, (j + 1) & 1);
            asm volatile("cp.async.wait_group 1;" ::: "memory");
        } else {
            asm volatile("cp.async.wait_group 0;" ::: "memory");
        }
        __syncthreads();
        if (j == 0) {   // Q frags -> registers, once
#pragma unroll
            for (int t = 0; t < 4; t++) {
                int row = w * 16 + rowA;
                uint32_t off = (uint32_t)row * 128 + (uint32_t)((((t * 2 + kA) ^ (row & 7))) << 4);
                ldsm4(sb + off, qf[t]);
            }
        }
        uint32_t base = sb + 16384 + (uint32_t)(j & 1) * 65536;

        // ---- S = Q (Kh+Kl)^T  (2 terms) ----
        float S[16][4];
#pragma unroll
        for (int a = 0; a < 16; a++)
#pragma unroll
            for (int b = 0; b < 4; b++) S[a][b] = 0.f;

#pragma unroll
        for (int np = 0; np < 8; np++) {
#pragma unroll
            for (int t = 0; t < 4; t++) {
                int row = np * 16 + rowB;
                uint32_t off = (uint32_t)row * 128 + (uint32_t)((((t * 2 + kB) ^ (row & 7))) << 4);
                uint32_t kh[4], kl[4];
                ldsm4(base + off,         kh);
                ldsm4(base + 16384 + off, kl);
                mma16816(S[2 * np],     qf[t], kh[0], kh[1]);
                mma16816(S[2 * np],     qf[t], kl[0], kl[1]);
                mma16816(S[2 * np + 1], qf[t], kh[2], kh[3]);
                mma16816(S[2 * np + 1], qf[t], kl[2], kl[3]);
            }
        }

        if (j == qb) {   // causal mask inside diagonal 128-block
            int r0 = w * 16 + g;
#pragma unroll
            for (int nf = 0; nf < 16; nf++) {
                int c0 = nf * 8 + 2 * (l & 3);
                if (c0     > r0)     S[nf][0] = -1e30f;
                if (c0 + 1 > r0)     S[nf][1] = -1e30f;
                if (c0     > r0 + 8) S[nf][2] = -1e30f;
                if (c0 + 1 > r0 + 8) S[nf][3] = -1e30f;
            }
        }

        // ---- online softmax ----
        float mx0 = -1e30f, mx1 = -1e30f;
#pragma unroll
        for (int nf = 0; nf < 16; nf++) {
            mx0 = fmaxf(mx0, fmaxf(S[nf][0], S[nf][1]));
            mx1 = fmaxf(mx1, fmaxf(S[nf][2], S[nf][3]));
        }
        mx0 = fmaxf(mx0, __shfl_xor_sync(0xffffffffu, mx0, 1));
        mx0 = fmaxf(mx0, __shfl_xor_sync(0xffffffffu, mx0, 2));
        mx1 = fmaxf(mx1, __shfl_xor_sync(0xffffffffu, mx1, 1));
        mx1 = fmaxf(mx1, __shfl_xor_sync(0xffffffffu, mx1, 2));
        float mn0 = fmaxf(mrow0, mx0), mn1 = fmaxf(mrow1, mx1);
        float cr0 = fexp2((mrow0 - mn0) * CE), cr1 = fexp2((mrow1 - mn1) * CE);
        mrow0 = mn0; mrow1 = mn1;
        float nm0 = mn0 * CE, nm1 = mn1 * CE;
#pragma unroll
        for (int nf = 0; nf < 8; nf++) {
            O[nf][0] *= cr0; O[nf][1] *= cr0;
            O[nf][2] *= cr1; O[nf][3] *= cr1;
        }
        float s0 = 0.f, s1 = 0.f;
        // exp; pack P as single-fp16 A-frags in place (S[2t][0..3] = frag)
#pragma unroll
        for (int t = 0; t < 8; t++) {
            float p00 = fexp2(fmaf(S[2*t][0],   CE, -nm0));
            float p01 = fexp2(fmaf(S[2*t][1],   CE, -nm0));
            float p02 = fexp2(fmaf(S[2*t][2],   CE, -nm1));
            float p03 = fexp2(fmaf(S[2*t][3],   CE, -nm1));
            float p10 = fexp2(fmaf(S[2*t+1][0], CE, -nm0));
            float p11 = fexp2(fmaf(S[2*t+1][1], CE, -nm0));
            float p12 = fexp2(fmaf(S[2*t+1][2], CE, -nm1));
            float p13 = fexp2(fmaf(S[2*t+1][3], CE, -nm1));
            s0 += (p00 + p01) + (p10 + p11);
            s1 += (p02 + p03) + (p12 + p13);
            S[2*t][0] = __uint_as_float(pkh(p00, p01));
            S[2*t][1] = __uint_as_float(pkh(p02, p03));
            S[2*t][2] = __uint_as_float(pkh(p10, p11));
            S[2*t][3] = __uint_as_float(pkh(p12, p13));
        }
        ls0 = ls0 * cr0 + s0;
        ls1 = ls1 * cr1 + s1;

        // ---- O += P (Vh+Vl)  (2 terms), V frags via ldmatrix.trans ----
#pragma unroll
        for (int t = 0; t < 8; t++) {
            uint32_t Af[4] = {__float_as_uint(S[2*t][0]), __float_as_uint(S[2*t][1]),
                              __float_as_uint(S[2*t][2]), __float_as_uint(S[2*t][3])};
#pragma unroll
            for (int vp = 0; vp < 4; vp++) {
                int row = t * 16 + rowV;
                uint32_t off = (uint32_t)row * 128 + (uint32_t)((((vp * 2 + cV) ^ (row & 7))) << 4);
                uint32_t vh[4], vl[4];
                ldsm4t(base + 32768 + off, vh);
                ldsm4t(base + 49152 + off, vl);
                mma16816(O[2 * vp],     Af, vh[0], vh[1]);
                mma16816(O[2 * vp],     Af, vl[0], vl[1]);
                mma16816(O[2 * vp + 1], Af, vh[2], vh[3]);
                mma16816(O[2 * vp + 1], Af, vl[2], vl[3]);
            }
        }
        __syncthreads();
    }

    // ---- finalize: reduce l across 4 lanes per row, write single-fp16 output ----
    ls0 += __shfl_xor_sync(0xffffffffu, ls0, 1);
    ls0 += __shfl_xor_sync(0xffffffffu, ls0, 2);
    ls1 += __shfl_xor_sync(0xffffffffu, ls1, 1);
    ls1 += __shfl_xor_sync(0xffffffffu, ls1, 2);
    float inv0 = 1.f / ls0, inv1 = 1.f / ls1;
    int r0 = qb * 128 + w * 16 + g;
#pragma unroll
    for (int nf = 0; nf < 8; nf++) {
        int col = nf * 8 + 2 * (l & 3);
        size_t o0 = (size_t)r0 * DM + hofs + col;
        size_t o1 = (size_t)(r0 + 8) * DM + hofs + col;
        *(uint32_t*)&oh[o0] = pkh(O[nf][0] * inv0, O[nf][1] * inv0);
        *(uint32_t*)&oh[o1] = pkh(O[nf][2] * inv1, O[nf][3] * inv1);
    }
}

// ---------------------------------------------------------------------------
extern "C" void kernel_launch(void* const* d_in, const int* in_sizes, int n_in,
                              void* d_out, int out_size)
{
    const float* x      = (const float*)d_in[0];
    // d_in[1] = additive causal mask — exactly causal, handled analytically
    const float* W_attn = (const float*)d_in[2];
    const float* b_attn = (const float*)d_in[3];
    const float* W_proj = (const float*)d_in[4];
    const float* b_proj = (const float*)d_in[5];
    float* out = (float*)d_out;

    __half *xh, *wah, *wal, *wph, *wpl, *qh, *ql, *ah;
    cudaGetSymbolAddress((void**)&xh, g_xh);
    cudaGetSymbolAddress((void**)&wah, g_wah); cudaGetSymbolAddress((void**)&wal, g_wal);
    cudaGetSymbolAddress((void**)&wph, g_wph); cudaGetSymbolAddress((void**)&wpl, g_wpl);
    cudaGetSymbolAddress((void**)&qh, g_qh);   cudaGetSymbolAddress((void**)&ql, g_ql);
    cudaGetSymbolAddress((void**)&ah, g_ah);

    static bool attr_done = false;
    if (!attr_done) {
        cudaFuncSetAttribute(mma_gemm<true>,  cudaFuncAttributeMaxDynamicSharedMemorySize, GEMM_SMEM);
        cudaFuncSetAttribute(mma_gemm<false>, cudaFuncAttributeMaxDynamicSharedMemorySize, GEMM_SMEM);
        cudaFuncSetAttribute(attn_mma, cudaFuncAttributeMaxDynamicSharedMemorySize, AT_SMEM);
        attr_done = true;
    }

    // pre-pass: x -> fp16 single; weights -> transposed fp16 hi/lo split
    int n4x = SLEN * DM / 4;
    cvt_h_kernel<<<(n4x + 255) / 256, 256>>>((const float4*)x, (uint2*)xh, n4x);
    tsplit_kernel<<<dim3(3 * DM / 32, DM / 32), dim3(32, 8)>>>(W_attn, wah, wal, DM, 3 * DM);
    tsplit_kernel<<<dim3(DM / 32, DM / 32), dim3(32, 8)>>>(W_proj, wph, wpl, DM, DM);

    // 1) QKV projection -> fp16 split qkv
    mma_gemm<false><<<dim3(3 * DM / 128, SLEN / 128), 256, GEMM_SMEM>>>(
        xh, wah, wal, b_attn, nullptr, qh, ql, SLEN, 3 * DM, DM);

    // 2) tensor-core flash attention -> fp16 single output
    attn_mma<<<dim3(32, 16), 256, AT_SMEM>>>(qh, ql, ah);

    // 3) output projection -> fp32
    mma_gemm<true><<<dim3(DM / 128, SLEN / 128), 256, GEMM_SMEM>>>(
        ah, wph, wpl, b_proj, out, nullptr, nullptr, SLEN, DM, DM);
}